// round 12
// baseline (speedup 1.0000x reference)
#include <cuda_runtime.h>
#include <cuda_fp16.h>
#include <mma.h>
#include <math.h>

using namespace nvcuda;

#define NN 100000
#define EE 800000
#define H  32
#define NL 4
#define FULL 0xffffffffu
#define SCAN_N   (NN + 1)
#define SCAN_NB  ((SCAN_N + 1023) / 1024)
#define SPLIT    1036          // blocks 0..SPLIT-1 = ce path; rest = gemm path
#define GRID_LF  1480

// ---------------- scratch ---------------------------------------------------------
__device__ float  g_h[NN*H];
__device__ float  g_hnew[NN*H];
__device__ float  g_Ah2[2][NN*H];  // double-buffered: ce(l) reads [(l-1)&1], gemm(l) writes [l&1]
__device__ float  g_Bh2[2][NN*H];
__device__ float  g_Uh[NN*H];      // tail: reused as hid_src (dead after agg2(l3))
__device__ float  g_Vh[NN*H];      // tail: reused as hid_dst
__device__ __half g_e[EE*H];       // e_l (dst-sorted)
__device__ __half g_ce[EE*H];      // Ce (fp16 storage, fp32 accum)
// stats slots: per layer l: [l*128 + 0:64) h sum/sq, [l*128+64:128) e sum/sq
__device__ float  g_stats[NL*128];
__device__ int    g_hist[SCAN_NB*1024];   // zero at load; setup re-zeros (leave-clean)
__device__ int    g_rowptr[NN+1];
__device__ int    g_cursor[NN];
__device__ int    g_bsum[SCAN_NB];
__device__ int    g_bar[4];               // spin-barrier counters (self-cleaning)
__device__ int    g_ssrc[EE];
__device__ int    g_sdst[EE];
__device__ int    g_oid[EE];

// ---------------- fused CSR build: hist -> scan -> scatter (one kernel) -----------
__global__ void __launch_bounds__(1024)
setup_fused(const int* __restrict__ src, const int* __restrict__ dst, int ne)
{
    __shared__ int sm[1024];
    int b = blockIdx.x, t = threadIdx.x;
    int nb = gridDim.x;
    int gid = b*1024 + t;
    int gsz = nb*1024;

    if (gid < NL*128) g_stats[gid] = 0.f;

    for (int i = gid; i < ne; i += gsz)
        atomicAdd(&g_hist[dst[i]], 1);

    __syncthreads();
    if (t == 0) {
        __threadfence();
        atomicAdd(&g_bar[0], 1);
        while (atomicAdd(&g_bar[0], 0) < nb) __nanosleep(64);
    }
    __syncthreads();

    int idx = gid;
    int v = (idx < SCAN_N) ? g_hist[idx] : 0;
    if (idx < SCAN_N) g_hist[idx] = 0;
    sm[t] = v;
    __syncthreads();
    for (int off = 1; off < 1024; off <<= 1) {
        int u = (t >= off) ? sm[t - off] : 0;
        __syncthreads();
        sm[t] += u;
        __syncthreads();
    }
    if (t == 1023) g_bsum[b] = sm[1023];
    __syncthreads();
    if (t == 0) {
        __threadfence();
        atomicAdd(&g_bar[1], 1);
        while (atomicAdd(&g_bar[1], 0) < nb) __nanosleep(64);
    }
    __syncthreads();
    int pre = 0;
    for (int i = 0; i < b; i++) pre += g_bsum[i];
    int excl = pre + sm[t] - v;
    if (idx < SCAN_N) {
        g_rowptr[idx] = excl;
        if (idx < NN) g_cursor[idx] = excl;
    }
    __syncthreads();
    if (t == 0) {
        __threadfence();
        atomicAdd(&g_bar[2], 1);
        while (atomicAdd(&g_bar[2], 0) < nb) __nanosleep(64);
    }
    __syncthreads();

    for (int i = gid; i < ne; i += gsz) {
        int d = dst[i];
        int pos = atomicAdd(&g_cursor[d], 1);
        g_ssrc[pos] = src[i];
        g_sdst[pos] = d;
        g_oid[pos]  = i;
    }

    __syncthreads();
    if (t == 0) {
        int done = atomicAdd(&g_bar[3], 1);
        if (done == nb - 1) {
            g_bar[0] = 0; g_bar[1] = 0; g_bar[2] = 0; g_bar[3] = 0;
            __threadfence();
        }
    }
}

// ===== heterogeneous layer kernel ==================================================
// Blocks [0, split):      ce path  — tensor-core edge GEMM -> fp16 ce.
//   eMode 1: project e from input (layer 0); store ce.
//   eMode 2: reconstruct enew_{l-1} = Ah[d]+Bh[s]+ce_prev (buffer ceBuf),
//            e += relu(BN(enew)), write e iff writeE; store ce.
// Blocks [split, grid):   gemm path (register weights, grid-stride)
//   gmode 0: h = x*pw+pb; 4 GEMMs -> Ah2[gBuf],Bh2[gBuf],Uh,Vh
//   gmode 1: h += relu(BN(hnew)); same 4 GEMMs
//   gmode 2: score pre-pass: h-update (not written back); 2 GEMMs with
//            W1[0:32]/W1[32:64] -> g_Uh (hid_src), g_Vh (hid_dst)
// ce reads buffer ceBuf, gemm writes buffer gBuf (or Uh/Vh) -> independent.
__global__ void __launch_bounds__(128)
layer_fused(const float* __restrict__ W, const float* __restrict__ bias,
            const float* __restrict__ bngE, const float* __restrict__ bnbE,
            const float* __restrict__ ein,
            const float* __restrict__ ew, const float* __restrict__ eb,
            int prevSlot, int eMode, int writeE,
            const float* __restrict__ Aw, const float* __restrict__ Ab,
            const float* __restrict__ Bw, const float* __restrict__ Bb,
            const float* __restrict__ Uw, const float* __restrict__ Ub,
            const float* __restrict__ Vw, const float* __restrict__ Vb,
            const float* __restrict__ bngH, const float* __restrict__ bnbH,
            const float* __restrict__ x,
            const float* __restrict__ pw, const float* __restrict__ pb,
            int statSlot, int gmode,
            int split, int ceBuf, int gBuf, int n, int ne, float inv_ne)
{
    __shared__ __half sWhi[32*32], sWlo[32*32];
    __shared__ __half sE[4][16*32];
    __shared__ float  sC[4][16*32];
    __shared__ float  sBias[32], sMn[32], sSc[32], sBt[32], sEw[32], sEb[32];

    int tid = threadIdx.x;
    int lane = tid & 31;

    if (blockIdx.x >= split) {
        // ================= gemm path =================
        int warp0  = (blockIdx.x - split) * 4 + (tid >> 5);
        int stride = (gridDim.x - split) * 4;

        if (gmode == 2) {
            float ws[32], wd[32];
            #pragma unroll
            for (int k = 0; k < 32; k++) {
                ws[k] = Aw[k*H + lane];   // W1[0:32]
                wd[k] = Bw[k*H + lane];   // W1[32:64]
            }
            float bb = Ab[lane];          // b1
            float inv = 1.0f / (float)n;
            float s1 = g_stats[statSlot*128 + lane];
            float s2 = g_stats[statSlot*128 + 32 + lane];
            float mn = s1 * inv;
            float var = s2 * inv - mn * mn;
            float sc = rsqrtf(var + 1e-5f) * bngH[lane];
            float bt = bnbH[lane];
            for (int row = warp0; row < n; row += stride) {
                float hv = g_h[row*H + lane];
                hv += fmaxf((g_hnew[row*H + lane] - mn) * sc + bt, 0.f);
                float a = bb, c = 0.f;
                #pragma unroll
                for (int k = 0; k < 32; k++) {
                    float hk = __shfl_sync(FULL, hv, k);
                    a += hk * ws[k];
                    c += hk * wd[k];
                }
                g_Uh[row*H + lane] = a;   // hid_src
                g_Vh[row*H + lane] = c;   // hid_dst
            }
            return;
        }

        float wA[32], wB[32], wU[32], wV[32];
        #pragma unroll
        for (int k = 0; k < 32; k++) {
            wA[k] = Aw[k*H + lane];
            wB[k] = Bw[k*H + lane];
            wU[k] = Uw[k*H + lane];
            wV[k] = Vw[k*H + lane];
        }
        float bA = Ab[lane], bB = Bb[lane], bU = Ub[lane], bV = Vb[lane];

        float mn = 0.f, sc = 0.f, bt = 0.f, pwl = 0.f, pbl = 0.f;
        if (gmode == 1) {
            float inv = 1.0f / (float)n;
            float s1 = g_stats[statSlot*128 + lane];
            float s2 = g_stats[statSlot*128 + 32 + lane];
            mn = s1 * inv;
            float var = s2 * inv - mn * mn;
            sc = rsqrtf(var + 1e-5f) * bngH[lane];
            bt = bnbH[lane];
        } else {
            pwl = pw[lane]; pbl = pb[lane];
        }

        float* dstA = g_Ah2[gBuf];
        float* dstB = g_Bh2[gBuf];
        for (int row = warp0; row < n; row += stride) {
            float hv;
            if (gmode == 0) {
                hv = x[row] * pwl + pbl;
                g_h[row*H + lane] = hv;
            } else {
                hv = g_h[row*H + lane];
                float v = (g_hnew[row*H + lane] - mn) * sc + bt;
                hv += fmaxf(v, 0.f);
                g_h[row*H + lane] = hv;
            }
            float a = bA, b = bB, u = bU, v = bV;
            #pragma unroll
            for (int k = 0; k < 32; k++) {
                float hk = __shfl_sync(FULL, hv, k);
                a += hk * wA[k];
                b += hk * wB[k];
                u += hk * wU[k];
                v += hk * wV[k];
            }
            dstA[row*H + lane] = a;
            dstB[row*H + lane] = b;
            g_Uh[row*H + lane] = u;
            g_Vh[row*H + lane] = v;
        }
        return;
    }

    // ================= ce path =================
    for (int i = tid; i < 1024; i += 128) {
        float w = W[i];
        __half hi = __float2half_rn(w);
        sWhi[i] = hi;
        sWlo[i] = __float2half_rn(w - __half2float(hi));
    }
    if (tid < 32) {
        sBias[tid] = bias ? bias[tid] : 0.f;
        sMn[tid] = 0.f; sSc[tid] = 0.f; sBt[tid] = 0.f;
        sEw[tid] = 0.f; sEb[tid] = 0.f;
        if (eMode == 2) {
            float s1 = g_stats[prevSlot*128 + 64 + tid];
            float s2 = g_stats[prevSlot*128 + 96 + tid];
            float mean = s1 * inv_ne;
            float var  = s2 * inv_ne - mean * mean;
            sMn[tid] = mean;
            sSc[tid] = rsqrtf(var + 1e-5f) * bngE[tid];
            sBt[tid] = bnbE[tid];
        } else {
            sEw[tid] = ew[tid]; sEb[tid] = eb[tid];
        }
    }
    __syncthreads();

    int warp = tid >> 5;

    wmma::fragment<wmma::matrix_b, 16,16,16, __half, wmma::row_major> bh[2][2], bl[2][2];
    #pragma unroll
    for (int kk = 0; kk < 2; kk++)
        #pragma unroll
        for (int nn = 0; nn < 2; nn++) {
            wmma::load_matrix_sync(bh[kk][nn], sWhi + kk*16*32 + nn*16, 32);
            wmma::load_matrix_sync(bl[kk][nn], sWlo + kk*16*32 + nn*16, 32);
        }

    const float* Ahp = g_Ah2[ceBuf];
    const float* Bhp = g_Bh2[ceBuf];
    __half2* e2  = (__half2*)g_e;
    __half2* ce2 = (__half2*)g_ce;
    int ntiles = (ne + 63) >> 6;

    for (int t = blockIdx.x; t < ntiles; t += split) {
        int rbase = t*64 + warp*16;
        __half2* stage = (__half2*)sE[warp];
        #pragma unroll
        for (int i = 0; i < 8; i++) {
            int idx = i*32 + lane;
            int row = rbase + (idx >> 4);
            int ch  = idx & 15;
            if (row < ne) {
                size_t g = (size_t)row*16 + ch;
                if (eMode == 1) {
                    float xin = ein[g_oid[row]];
                    int c = ch*2;
                    __half2 nv = __floats2half2_rn(xin*sEw[c] + sEb[c],
                                                   xin*sEw[c+1] + sEb[c+1]);
                    e2[g] = nv;
                    stage[idx] = nv;
                } else {
                    int s = g_ssrc[row], d = g_sdst[row];
                    int c = ch*2;
                    float2 ah  = *(const float2*)(Ahp + d*H + c);
                    float2 bhv = *(const float2*)(Bhp + s*H + c);
                    float2 ce  = __half22float2(ce2[g]);
                    float enx = ah.x + bhv.x + ce.x;
                    float eny = ah.y + bhv.y + ce.y;
                    float2 f = __half22float2(e2[g]);
                    f.x += fmaxf((enx - sMn[c])   * sSc[c]   + sBt[c],   0.f);
                    f.y += fmaxf((eny - sMn[c+1]) * sSc[c+1] + sBt[c+1], 0.f);
                    __half2 nv = __floats2half2_rn(f.x, f.y);
                    if (writeE) e2[g] = nv;
                    stage[idx] = nv;
                }
            } else {
                stage[idx] = __floats2half2_rn(0.f, 0.f);
            }
        }
        __syncwarp();

        wmma::fragment<wmma::matrix_a, 16,16,16, __half, wmma::row_major> a0, a1;
        wmma::load_matrix_sync(a0, sE[warp],      32);
        wmma::load_matrix_sync(a1, sE[warp] + 16, 32);

        wmma::fragment<wmma::accumulator, 16,16,16, float> acc0, acc1;
        wmma::fill_fragment(acc0, 0.f);
        wmma::fill_fragment(acc1, 0.f);
        wmma::mma_sync(acc0, a0, bh[0][0], acc0);
        wmma::mma_sync(acc0, a1, bh[1][0], acc0);
        wmma::mma_sync(acc0, a0, bl[0][0], acc0);
        wmma::mma_sync(acc0, a1, bl[1][0], acc0);
        wmma::mma_sync(acc1, a0, bh[0][1], acc1);
        wmma::mma_sync(acc1, a1, bh[1][1], acc1);
        wmma::mma_sync(acc1, a0, bl[0][1], acc1);
        wmma::mma_sync(acc1, a1, bl[1][1], acc1);

        wmma::store_matrix_sync(sC[warp],      acc0, 32, wmma::mem_row_major);
        wmma::store_matrix_sync(sC[warp] + 16, acc1, 32, wmma::mem_row_major);
        __syncwarp();

        #pragma unroll
        for (int r = 0; r < 16; r++) {
            int row = rbase + r;
            if (row < ne)
                g_ce[(size_t)row*32 + lane] =
                    __float2half_rn(sC[warp][r*32 + lane] + sBias[lane]);
        }
        __syncwarp();
    }
}

// ---- aggregation: warp per node; enew computed inline, NOT stored ----------------
__global__ void agg2(int curSlot, int cur, int n)
{
    int lane = threadIdx.x & 31;

    __shared__ float sE[32], qE[32], sH[32], qH[32];
    if (threadIdx.x < 32) {
        sE[threadIdx.x] = 0.f; qE[threadIdx.x] = 0.f;
        sH[threadIdx.x] = 0.f; qH[threadIdx.x] = 0.f;
    }
    __syncthreads();

    const float* Ahp = g_Ah2[cur];
    const float* Bhp = g_Bh2[cur];
    float ls = 0.f, lq = 0.f, hs = 0.f, hq = 0.f;
    int d = blockIdx.x * (blockDim.x >> 5) + (threadIdx.x >> 5);
    if (d < n) {
        int beg = g_rowptr[d], end = g_rowptr[d+1];
        float ah = Ahp[d*H + lane];
        float uh = g_Uh[d*H + lane];
        float num = 0.f, den = 0.f;
        int i = beg;
        for (; i + 3 < end; i += 4) {
            int   s[4];
            float ce[4], bh[4], vh[4];
            #pragma unroll
            for (int j = 0; j < 4; j++) s[j] = g_ssrc[i+j];
            #pragma unroll
            for (int j = 0; j < 4; j++) ce[j] = __half2float(g_ce[(size_t)(i+j)*H + lane]);
            #pragma unroll
            for (int j = 0; j < 4; j++) bh[j] = Bhp[s[j]*H + lane];
            #pragma unroll
            for (int j = 0; j < 4; j++) vh[j] = g_Vh[s[j]*H + lane];
            #pragma unroll
            for (int j = 0; j < 4; j++) {
                float en = ah + bh[j] + ce[j];
                ls += en; lq += en * en;
                float sg = 1.0f / (1.0f + __expf(-en));
                num += sg * vh[j];
                den += sg;
            }
        }
        for (; i < end; i++) {
            int s0 = g_ssrc[i];
            float en = ah + Bhp[s0*H + lane] + __half2float(g_ce[(size_t)i*H + lane]);
            ls += en; lq += en * en;
            float sg0 = 1.0f / (1.0f + __expf(-en));
            num += sg0 * g_Vh[s0*H + lane];
            den += sg0;
        }
        float hn = uh + num / (den + 1e-6f);
        g_hnew[d*H + lane] = hn;
        hs += hn; hq += hn * hn;
    }
    atomicAdd(&sH[lane], hs); atomicAdd(&qH[lane], hq);
    atomicAdd(&sE[lane], ls); atomicAdd(&qE[lane], lq);
    __syncthreads();
    if (threadIdx.x < 32) {
        atomicAdd(&g_stats[curSlot*128 + threadIdx.x],      sH[threadIdx.x]);
        atomicAdd(&g_stats[curSlot*128 + 32 + threadIdx.x], qH[threadIdx.x]);
        atomicAdd(&g_stats[curSlot*128 + 64 + threadIdx.x], sE[threadIdx.x]);
        atomicAdd(&g_stats[curSlot*128 + 96 + threadIdx.x], qE[threadIdx.x]);
    }
}

// ---- score: hid = relu(hid_s[s] + hid_d[d] + ce); out = hid @ W2 + b2 ------------
__global__ void score_final(const float* __restrict__ W2, const float* __restrict__ b2,
                            float* __restrict__ out, int ne)
{
    int lane = threadIdx.x & 31;
    float w2 = W2[lane];
    float bb2 = b2[0];

    int i = blockIdx.x * (blockDim.x >> 5) + (threadIdx.x >> 5);
    if (i >= ne) return;
    int s = g_ssrc[i], d = g_sdst[i], o = g_oid[i];
    float hid = g_Uh[s*H + lane] + g_Vh[d*H + lane]
              + __half2float(g_ce[(size_t)i*H + lane]);
    hid = fmaxf(hid, 0.f);
    float p = hid * w2;
    #pragma unroll
    for (int off = 16; off > 0; off >>= 1)
        p += __shfl_xor_sync(FULL, p, off);
    if (lane == 0) out[o] = p + bb2;
}

// ==================================================================================
extern "C" void kernel_launch(void* const* d_in, const int* in_sizes, int n_in,
                              void* d_out, int out_size)
{
    const float* x    = (const float*)d_in[0];
    const float* ein  = (const float*)d_in[1];
    const int*   eidx = (const int*)  d_in[2];
    const float* pe_w = (const float*)d_in[3];
    const float* pe_b = (const float*)d_in[4];
    const float* ed_w = (const float*)d_in[5];
    const float* ed_b = (const float*)d_in[6];
    const float* A_w  = (const float*)d_in[7];
    const float* A_b  = (const float*)d_in[8];
    const float* B_w  = (const float*)d_in[9];
    const float* B_b  = (const float*)d_in[10];
    const float* C_w  = (const float*)d_in[11];
    const float* C_b  = (const float*)d_in[12];
    const float* U_w  = (const float*)d_in[13];
    const float* U_b  = (const float*)d_in[14];
    const float* V_w  = (const float*)d_in[15];
    const float* V_b  = (const float*)d_in[16];
    const float* bnhg = (const float*)d_in[17];
    const float* bnhb = (const float*)d_in[18];
    const float* bneg = (const float*)d_in[19];
    const float* bneb = (const float*)d_in[20];
    const float* W1_w = (const float*)d_in[21];
    const float* W1_b = (const float*)d_in[22];
    const float* W2_w = (const float*)d_in[23];
    const float* W2_b = (const float*)d_in[24];
    float* out = (float*)d_out;

    const int n  = in_sizes[0];
    const int ne = in_sizes[1];
    const int* src = eidx;
    const int* dst = eidx + ne;
    const float inv_ne = 1.0f / (float)ne;

    const int TB = 256;
    const int WPB = TB / 32;
    const int G_NODE_W = (n  + WPB - 1) / WPB;
    const int G_EDGE_W = (ne + WPB - 1) / WPB;

    // ---- fused CSR build: 1 launch ----
    setup_fused<<<SCAN_NB, 1024>>>(src, dst, ne);              // #1

    for (int l = 0; l < NL; l++) {
        int cur = l & 1;
        // ce path reads Ah2/Bh2[cur^1]; gemm path writes Ah2/Bh2[cur] -> independent
        layer_fused<<<GRID_LF, 128>>>(
            C_w + l*H*H, C_b + l*H,
            bneg + (l-1)*H, bneb + (l-1)*H,
            ein, ed_w, ed_b,
            l-1, l == 0 ? 1 : 2, /*writeE=*/1,
            A_w + l*H*H, A_b + l*H, B_w + l*H*H, B_b + l*H,
            U_w + l*H*H, U_b + l*H, V_w + l*H*H, V_b + l*H,
            bnhg + (l-1)*H, bnhb + (l-1)*H,
            x, pe_w, pe_b,
            l-1, l == 0 ? 0 : 1,
            SPLIT, /*ceBuf=*/cur^1, /*gBuf=*/cur, n, ne, inv_ne);

        agg2<<<G_NODE_W, TB>>>(l, cur, n);
    }

    // tail: final edge GEMM reads layer-3 buffers Ah2/Bh2[(NL-1)&1 = 1];
    // score pre-pass (gmode 2) writes hid into g_Uh/g_Vh -> no overlap with ce reads.
    layer_fused<<<GRID_LF, 128>>>(
        W1_w + 64*32, (const float*)nullptr,
        bneg + (NL-1)*H, bneb + (NL-1)*H,
        (const float*)nullptr, (const float*)nullptr, (const float*)nullptr,
        NL-1, /*eMode=*/2, /*writeE=*/0,
        W1_w, W1_b, W1_w + 32*32, (const float*)nullptr,
        (const float*)nullptr, (const float*)nullptr,
        (const float*)nullptr, (const float*)nullptr,
        bnhg + (NL-1)*H, bnhb + (NL-1)*H,
        (const float*)nullptr, (const float*)nullptr, (const float*)nullptr,
        NL-1, /*gmode=*/2,
        SPLIT, /*ceBuf=*/(NL-1)&1, /*gBuf=*/0 /*unused*/, n, ne, inv_ne);

    score_final<<<G_EDGE_W, TB>>>(W2_w, W2_b, out, ne);
}

// round 13
// speedup vs baseline: 1.3299x; 1.3299x over previous
#include <cuda_runtime.h>
#include <cuda_fp16.h>
#include <mma.h>
#include <math.h>

using namespace nvcuda;

#define NN 100000
#define EE 800000
#define H  32
#define NL 4
#define FULL 0xffffffffu
#define SCAN_N   (NN + 1)
#define SCAN_NB  ((SCAN_N + 1023) / 1024)

// ---------------- scratch ---------------------------------------------------------
__device__ float  g_h[NN*H];
__device__ float  g_hnew[NN*H];
__device__ float  g_Ah[NN*H];
__device__ float  g_Bh[NN*H];
__device__ float  g_Uh[NN*H];
__device__ float  g_Vh[NN*H];
__device__ __half g_e[EE*H];       // e_l (dst-sorted)
__device__ __half g_ce[EE*H];      // Ce (fp16 storage, fp32 accum); enew reconstructed
// stats slots: per layer l: [l*128 + 0:64) h sum/sq, [l*128+64:128) e sum/sq
__device__ float  g_stats[NL*128];
__device__ int    g_hist[SCAN_NB*1024];   // zero at load; setup re-zeros (leave-clean)
__device__ int    g_rowptr[NN+1];
__device__ int    g_cursor[NN];
__device__ int    g_bsum[SCAN_NB];
__device__ int    g_bar[4];               // spin-barrier counters (self-cleaning)
__device__ int    g_ssrc[EE];
__device__ int    g_sdst[EE];
__device__ int    g_oid[EE];

// ---------------- fused CSR build: hist -> scan -> scatter (one kernel) -----------
// 98 blocks x 1024 threads; all co-resident on 148 SMs, so spin barriers are safe.
__global__ void __launch_bounds__(1024)
setup_fused(const int* __restrict__ src, const int* __restrict__ dst, int ne)
{
    __shared__ int sm[1024];
    int b = blockIdx.x, t = threadIdx.x;
    int nb = gridDim.x;
    int gid = b*1024 + t;
    int gsz = nb*1024;

    if (gid < NL*128) g_stats[gid] = 0.f;

    // ---- phase 1: histogram ----
    for (int i = gid; i < ne; i += gsz)
        atomicAdd(&g_hist[dst[i]], 1);

    __syncthreads();
    if (t == 0) {
        __threadfence();
        atomicAdd(&g_bar[0], 1);
        while (atomicAdd(&g_bar[0], 0) < nb) __nanosleep(64);
    }
    __syncthreads();

    // ---- phase 2: exclusive scan ----
    int idx = gid;
    int v = (idx < SCAN_N) ? g_hist[idx] : 0;
    if (idx < SCAN_N) g_hist[idx] = 0;        // leave clean for next replay
    sm[t] = v;
    __syncthreads();
    for (int off = 1; off < 1024; off <<= 1) {
        int u = (t >= off) ? sm[t - off] : 0;
        __syncthreads();
        sm[t] += u;
        __syncthreads();
    }
    if (t == 1023) g_bsum[b] = sm[1023];
    __syncthreads();
    if (t == 0) {
        __threadfence();
        atomicAdd(&g_bar[1], 1);
        while (atomicAdd(&g_bar[1], 0) < nb) __nanosleep(64);
    }
    __syncthreads();
    int pre = 0;
    for (int i = 0; i < b; i++) pre += g_bsum[i];
    int excl = pre + sm[t] - v;
    if (idx < SCAN_N) {
        g_rowptr[idx] = excl;
        if (idx < NN) g_cursor[idx] = excl;
    }
    __syncthreads();
    if (t == 0) {
        __threadfence();
        atomicAdd(&g_bar[2], 1);
        while (atomicAdd(&g_bar[2], 0) < nb) __nanosleep(64);
    }
    __syncthreads();

    // ---- phase 3: scatter ----
    for (int i = gid; i < ne; i += gsz) {
        int d = dst[i];
        int pos = atomicAdd(&g_cursor[d], 1);
        g_ssrc[pos] = src[i];
        g_sdst[pos] = d;
        g_oid[pos]  = i;
    }

    __syncthreads();
    if (t == 0) {
        int done = atomicAdd(&g_bar[3], 1);
        if (done == nb - 1) {
            g_bar[0] = 0; g_bar[1] = 0; g_bar[2] = 0; g_bar[3] = 0;
            __threadfence();
        }
    }
}

// ------- gemm4: weights in REGISTERS (zero LDS); grid-stride over rows -----------
__global__ void __launch_bounds__(128)
gemm4_fused(const float* __restrict__ Aw, const float* __restrict__ Ab,
            const float* __restrict__ Bw, const float* __restrict__ Bb,
            const float* __restrict__ Uw, const float* __restrict__ Ub,
            const float* __restrict__ Vw, const float* __restrict__ Vb,
            const float* __restrict__ bng, const float* __restrict__ bnb,
            const float* __restrict__ x,
            const float* __restrict__ pw, const float* __restrict__ pb,
            int statSlot, int mode /*0=proj,1=update*/, int n)
{
    int lane = threadIdx.x & 31;
    float wA[32], wB[32], wU[32], wV[32];
    #pragma unroll
    for (int k = 0; k < 32; k++) {
        wA[k] = Aw[k*H + lane];
        wB[k] = Bw[k*H + lane];
        wU[k] = Uw[k*H + lane];
        wV[k] = Vw[k*H + lane];
    }
    float bA = Ab[lane], bB = Bb[lane], bU = Ub[lane], bV = Vb[lane];

    float mn = 0.f, sc = 0.f, bt = 0.f, pwl = 0.f, pbl = 0.f;
    if (mode == 1) {
        float inv = 1.0f / (float)n;
        float s1 = g_stats[statSlot*128 + lane];
        float s2 = g_stats[statSlot*128 + 32 + lane];
        mn = s1 * inv;
        float var = s2 * inv - mn * mn;
        sc = rsqrtf(var + 1e-5f) * bng[lane];
        bt = bnb[lane];
    } else {
        pwl = pw[lane]; pbl = pb[lane];
    }

    int warp0  = blockIdx.x * (blockDim.x >> 5) + (threadIdx.x >> 5);
    int stride = gridDim.x * (blockDim.x >> 5);
    for (int row = warp0; row < n; row += stride) {
        float hv;
        if (mode == 0) {
            hv = x[row] * pwl + pbl;
            g_h[row*H + lane] = hv;
        } else {
            hv = g_h[row*H + lane];
            float v = (g_hnew[row*H + lane] - mn) * sc + bt;
            hv += fmaxf(v, 0.f);
            g_h[row*H + lane] = hv;
        }
        float a = bA, b = bB, u = bU, v = bV;
        #pragma unroll
        for (int k = 0; k < 32; k++) {
            float hk = __shfl_sync(FULL, hv, k);
            a += hk * wA[k];
            b += hk * wB[k];
            u += hk * wU[k];
            v += hk * wV[k];
        }
        g_Ah[row*H + lane] = a;
        g_Bh[row*H + lane] = b;
        g_Uh[row*H + lane] = u;
        g_Vh[row*H + lane] = v;
    }
}

// ---- tensor-core edge GEMM -> fp16 ce. N-split (2 x 16-col halves, unroll 1) to
// ---- cap live fragments at ~1 acc + 4 B -> lower regs -> higher occupancy.
// eMode 1: project e from input (layer 0); store ce.
// eMode 2: reconstruct enew_{l-1} = Ah[d]+Bh[s]+ce_prev, apply e += relu(BN(enew));
//          write e back iff writeE. Must run BEFORE next layer's gemm4.
__global__ void __launch_bounds__(128)
ce_mma(const float* __restrict__ W, const float* __restrict__ bias,
       const float* __restrict__ bng, const float* __restrict__ bnb,
       const float* __restrict__ ein,
       const float* __restrict__ ew, const float* __restrict__ eb,
       int prevSlot, int eMode, int writeE, int ne, float inv_ne)
{
    __shared__ __half sWhi[32*32], sWlo[32*32];
    __shared__ __half sE[4][16*32];
    __shared__ float  sC[4][16*32];
    __shared__ float  sBias[32], sMn[32], sSc[32], sBt[32], sEw[32], sEb[32];

    int tid = threadIdx.x;
    for (int i = tid; i < 1024; i += 128) {
        float w = W[i];
        __half hi = __float2half_rn(w);
        sWhi[i] = hi;
        sWlo[i] = __float2half_rn(w - __half2float(hi));
    }
    if (tid < 32) {
        sBias[tid] = bias ? bias[tid] : 0.f;
        sMn[tid] = 0.f; sSc[tid] = 0.f; sBt[tid] = 0.f;
        sEw[tid] = 0.f; sEb[tid] = 0.f;
        if (eMode == 2) {
            float s1 = g_stats[prevSlot*128 + 64 + tid];
            float s2 = g_stats[prevSlot*128 + 96 + tid];
            float mean = s1 * inv_ne;
            float var  = s2 * inv_ne - mean * mean;
            sMn[tid] = mean;
            sSc[tid] = rsqrtf(var + 1e-5f) * bng[tid];
            sBt[tid] = bnb[tid];
        } else {
            sEw[tid] = ew[tid]; sEb[tid] = eb[tid];
        }
    }
    __syncthreads();

    int warp = tid >> 5, lane = tid & 31;

    __half2* e2  = (__half2*)g_e;
    __half2* ce2 = (__half2*)g_ce;
    int ntiles = (ne + 63) >> 6;

    for (int t = blockIdx.x; t < ntiles; t += gridDim.x) {
        int rbase = t*64 + warp*16;
        __half2* stage = (__half2*)sE[warp];
        #pragma unroll
        for (int i = 0; i < 8; i++) {
            int idx = i*32 + lane;
            int row = rbase + (idx >> 4);
            int ch  = idx & 15;
            if (row < ne) {
                size_t g = (size_t)row*16 + ch;
                if (eMode == 1) {
                    float xin = ein[g_oid[row]];
                    int c = ch*2;
                    __half2 nv = __floats2half2_rn(xin*sEw[c] + sEb[c],
                                                   xin*sEw[c+1] + sEb[c+1]);
                    e2[g] = nv;
                    stage[idx] = nv;
                } else {
                    int s = g_ssrc[row], d = g_sdst[row];
                    int c = ch*2;
                    float2 ah  = *(const float2*)(g_Ah + d*H + c);
                    float2 bhv = *(const float2*)(g_Bh + s*H + c);
                    float2 ce  = __half22float2(ce2[g]);
                    float enx = ah.x + bhv.x + ce.x;
                    float eny = ah.y + bhv.y + ce.y;
                    float2 f = __half22float2(e2[g]);
                    f.x += fmaxf((enx - sMn[c])   * sSc[c]   + sBt[c],   0.f);
                    f.y += fmaxf((eny - sMn[c+1]) * sSc[c+1] + sBt[c+1], 0.f);
                    __half2 nv = __floats2half2_rn(f.x, f.y);
                    if (writeE) e2[g] = nv;
                    stage[idx] = nv;
                }
            } else {
                stage[idx] = __floats2half2_rn(0.f, 0.f);
            }
        }
        __syncwarp();

        wmma::fragment<wmma::matrix_a, 16,16,16, __half, wmma::row_major> a0, a1;
        wmma::load_matrix_sync(a0, sE[warp],      32);
        wmma::load_matrix_sync(a1, sE[warp] + 16, 32);

        // N-split: process 16 output columns at a time; unroll 1 keeps only
        // 4 B-fragments + 1 accumulator live -> lower register pressure.
        #pragma unroll 1
        for (int nh = 0; nh < 2; nh++) {
            wmma::fragment<wmma::matrix_b, 16,16,16, __half, wmma::row_major> fbh0, fbh1, fbl0, fbl1;
            wmma::load_matrix_sync(fbh0, sWhi + nh*16,           32);
            wmma::load_matrix_sync(fbh1, sWhi + 16*32 + nh*16,   32);
            wmma::load_matrix_sync(fbl0, sWlo + nh*16,           32);
            wmma::load_matrix_sync(fbl1, sWlo + 16*32 + nh*16,   32);

            wmma::fragment<wmma::accumulator, 16,16,16, float> acc;
            wmma::fill_fragment(acc, 0.f);
            wmma::mma_sync(acc, a0, fbh0, acc);
            wmma::mma_sync(acc, a1, fbh1, acc);
            wmma::mma_sync(acc, a0, fbl0, acc);
            wmma::mma_sync(acc, a1, fbl1, acc);

            wmma::store_matrix_sync(sC[warp] + nh*16, acc, 32, wmma::mem_row_major);
        }
        __syncwarp();

        #pragma unroll
        for (int r = 0; r < 16; r++) {
            int row = rbase + r;
            if (row < ne)
                g_ce[(size_t)row*32 + lane] =
                    __float2half_rn(sC[warp][r*32 + lane] + sBias[lane]);
        }
        __syncwarp();
    }
}

// ---- aggregation: warp per node; enew computed inline, NOT stored ----------------
__global__ void agg2(int curSlot, int n)
{
    int lane = threadIdx.x & 31;

    __shared__ float sE[32], qE[32], sH[32], qH[32];
    if (threadIdx.x < 32) {
        sE[threadIdx.x] = 0.f; qE[threadIdx.x] = 0.f;
        sH[threadIdx.x] = 0.f; qH[threadIdx.x] = 0.f;
    }
    __syncthreads();

    float ls = 0.f, lq = 0.f, hs = 0.f, hq = 0.f;
    int d = blockIdx.x * (blockDim.x >> 5) + (threadIdx.x >> 5);
    if (d < n) {
        int beg = g_rowptr[d], end = g_rowptr[d+1];
        float ah = g_Ah[d*H + lane];
        float uh = g_Uh[d*H + lane];
        float num = 0.f, den = 0.f;
        int i = beg;
        for (; i + 3 < end; i += 4) {
            int   s[4];
            float ce[4], bh[4], vh[4];
            #pragma unroll
            for (int j = 0; j < 4; j++) s[j] = g_ssrc[i+j];
            #pragma unroll
            for (int j = 0; j < 4; j++) ce[j] = __half2float(g_ce[(size_t)(i+j)*H + lane]);
            #pragma unroll
            for (int j = 0; j < 4; j++) bh[j] = g_Bh[s[j]*H + lane];
            #pragma unroll
            for (int j = 0; j < 4; j++) vh[j] = g_Vh[s[j]*H + lane];
            #pragma unroll
            for (int j = 0; j < 4; j++) {
                float en = ah + bh[j] + ce[j];
                ls += en; lq += en * en;
                float sg = 1.0f / (1.0f + __expf(-en));
                num += sg * vh[j];
                den += sg;
            }
        }
        for (; i < end; i++) {
            int s0 = g_ssrc[i];
            float en = ah + g_Bh[s0*H + lane] + __half2float(g_ce[(size_t)i*H + lane]);
            ls += en; lq += en * en;
            float sg0 = 1.0f / (1.0f + __expf(-en));
            num += sg0 * g_Vh[s0*H + lane];
            den += sg0;
        }
        float hn = uh + num / (den + 1e-6f);
        g_hnew[d*H + lane] = hn;
        hs += hn; hq += hn * hn;
    }
    atomicAdd(&sH[lane], hs); atomicAdd(&qH[lane], hq);
    atomicAdd(&sE[lane], ls); atomicAdd(&qE[lane], lq);
    __syncthreads();
    if (threadIdx.x < 32) {
        atomicAdd(&g_stats[curSlot*128 + threadIdx.x],      sH[threadIdx.x]);
        atomicAdd(&g_stats[curSlot*128 + 32 + threadIdx.x], qH[threadIdx.x]);
        atomicAdd(&g_stats[curSlot*128 + 64 + threadIdx.x], sE[threadIdx.x]);
        atomicAdd(&g_stats[curSlot*128 + 96 + threadIdx.x], qE[threadIdx.x]);
    }
}

// ---- score pre-pass: final h-update fused; hid_src -> g_Ah, hid_dst -> g_Bh ------
// (runs AFTER the final ce_mma, which needs the old Ah/Bh)
__global__ void __launch_bounds__(128)
score_gemm2(const float* __restrict__ W1, const float* __restrict__ b1,
            const float* __restrict__ bng, const float* __restrict__ bnb,
            int statSlot, int n)
{
    int lane = threadIdx.x & 31;
    float ws[32], wd[32];
    #pragma unroll
    for (int k = 0; k < 32; k++) {
        ws[k] = W1[k*32 + lane];
        wd[k] = W1[(32 + k)*32 + lane];
    }
    float bb = b1[lane];
    float inv = 1.0f / (float)n;
    float s1 = g_stats[statSlot*128 + lane];
    float s2 = g_stats[statSlot*128 + 32 + lane];
    float mn = s1 * inv;
    float var = s2 * inv - mn * mn;
    float sc = rsqrtf(var + 1e-5f) * bng[lane];
    float bt = bnb[lane];

    int warp0  = blockIdx.x * (blockDim.x >> 5) + (threadIdx.x >> 5);
    int stride = gridDim.x * (blockDim.x >> 5);
    for (int row = warp0; row < n; row += stride) {
        float hv = g_h[row*H + lane];
        hv += fmaxf((g_hnew[row*H + lane] - mn) * sc + bt, 0.f);
        float a = bb, c = 0.f;
        #pragma unroll
        for (int k = 0; k < 32; k++) {
            float hk = __shfl_sync(FULL, hv, k);
            a += hk * ws[k];
            c += hk * wd[k];
        }
        g_Ah[row*H + lane] = a;
        g_Bh[row*H + lane] = c;
    }
}

// ---- score: hid = relu(hid_s + hid_d + hid_e); out = hid @ W2 + b2 ---------------
__global__ void score_final(const float* __restrict__ W2, const float* __restrict__ b2,
                            float* __restrict__ out, int ne)
{
    int lane = threadIdx.x & 31;
    float w2 = W2[lane];
    float bb2 = b2[0];

    int i = blockIdx.x * (blockDim.x >> 5) + (threadIdx.x >> 5);
    if (i >= ne) return;
    int s = g_ssrc[i], d = g_sdst[i], o = g_oid[i];
    float hid = g_Ah[s*H + lane] + g_Bh[d*H + lane]
              + __half2float(g_ce[(size_t)i*H + lane]);
    hid = fmaxf(hid, 0.f);
    float p = hid * w2;
    #pragma unroll
    for (int off = 16; off > 0; off >>= 1)
        p += __shfl_xor_sync(FULL, p, off);
    if (lane == 0) out[o] = p + bb2;
}

// ==================================================================================
extern "C" void kernel_launch(void* const* d_in, const int* in_sizes, int n_in,
                              void* d_out, int out_size)
{
    const float* x    = (const float*)d_in[0];
    const float* ein  = (const float*)d_in[1];
    const int*   eidx = (const int*)  d_in[2];
    const float* pe_w = (const float*)d_in[3];
    const float* pe_b = (const float*)d_in[4];
    const float* ed_w = (const float*)d_in[5];
    const float* ed_b = (const float*)d_in[6];
    const float* A_w  = (const float*)d_in[7];
    const float* A_b  = (const float*)d_in[8];
    const float* B_w  = (const float*)d_in[9];
    const float* B_b  = (const float*)d_in[10];
    const float* C_w  = (const float*)d_in[11];
    const float* C_b  = (const float*)d_in[12];
    const float* U_w  = (const float*)d_in[13];
    const float* U_b  = (const float*)d_in[14];
    const float* V_w  = (const float*)d_in[15];
    const float* V_b  = (const float*)d_in[16];
    const float* bnhg = (const float*)d_in[17];
    const float* bnhb = (const float*)d_in[18];
    const float* bneg = (const float*)d_in[19];
    const float* bneb = (const float*)d_in[20];
    const float* W1_w = (const float*)d_in[21];
    const float* W1_b = (const float*)d_in[22];
    const float* W2_w = (const float*)d_in[23];
    const float* W2_b = (const float*)d_in[24];
    float* out = (float*)d_out;

    const int n  = in_sizes[0];
    const int ne = in_sizes[1];
    const int* src = eidx;
    const int* dst = eidx + ne;
    const float inv_ne = 1.0f / (float)ne;

    const int TB = 256;
    const int WPB = TB / 32;
    const int G_NODE_W = (n  + WPB - 1) / WPB;
    const int G_EDGE_W = (ne + WPB - 1) / WPB;
    const int G_MMA = 1480;
    const int G_G4  = 1480;

    // ---- fused CSR build: 1 launch ----
    setup_fused<<<SCAN_NB, 1024>>>(src, dst, ne);

    for (int l = 0; l < NL; l++) {
        // ce_mma BEFORE gemm4: eMode 2 reconstructs enew_{l-1} from old Ah/Bh.
        ce_mma<<<G_MMA, 128>>>(C_w + l*H*H, C_b + l*H,
                               bneg + (l-1)*H, bneb + (l-1)*H,
                               ein, ed_w, ed_b,
                               l-1, l == 0 ? 1 : 2, /*writeE=*/1, ne, inv_ne);

        gemm4_fused<<<G_G4, 128>>>(A_w + l*H*H, A_b + l*H,
                                   B_w + l*H*H, B_b + l*H,
                                   U_w + l*H*H, U_b + l*H,
                                   V_w + l*H*H, V_b + l*H,
                                   bnhg + (l-1)*H, bnhb + (l-1)*H,
                                   x, pe_w, pe_b,
                                   l-1, l == 0 ? 0 : 1, n);

        agg2<<<G_NODE_W, TB>>>(l, n);
    }

    // final edge term BEFORE score_gemm2 (needs Ah_3/Bh_3 for enew reconstruction)
    ce_mma<<<G_MMA, 128>>>(W1_w + 64*32, (const float*)nullptr,
                           bneg + (NL-1)*H, bneb + (NL-1)*H,
                           (const float*)nullptr, (const float*)nullptr,
                           (const float*)nullptr,
                           NL-1, /*eMode=*/2, /*writeE=*/0, ne, inv_ne);
    score_gemm2<<<G_G4, 128>>>(W1_w, W1_b,
                               bnhg + (NL-1)*H, bnhb + (NL-1)*H, NL-1, n);
    score_final<<<G_EDGE_W, TB>>>(W2_w, W2_b, out, ne);
}

// round 14
// speedup vs baseline: 1.3571x; 1.0205x over previous
#include <cuda_runtime.h>
#include <cuda_fp16.h>
#include <mma.h>
#include <math.h>

using namespace nvcuda;

#define NN 100000
#define EE 800000
#define H  32
#define NL 4
#define FULL 0xffffffffu
#define SCAN_N   (NN + 1)
#define SCAN_NB  ((SCAN_N + 1023) / 1024)

// ---------------- scratch ---------------------------------------------------------
__device__ float  g_h[NN*H];
__device__ float  g_hnew[NN*H];
__device__ float  g_Ah[NN*H];
__device__ float  g_Bh[NN*H];      // ce_mma staging reads (contiguous float2)
__device__ float  g_Uh[NN*H];
__device__ float  g_BV[NN*H*2];    // interleaved {Bh,Vh} per (row,lane) for agg2 gathers
__device__ __half g_e[EE*H];       // e_l (dst-sorted)
__device__ __half g_ce[EE*H];      // Ce (fp16 storage, fp32 accum); enew reconstructed
// stats slots: per layer l: [l*128 + 0:64) h sum/sq, [l*128+64:128) e sum/sq
__device__ float  g_stats[NL*128];
__device__ int    g_hist[SCAN_NB*1024];   // zero at load; setup re-zeros (leave-clean)
__device__ int    g_rowptr[NN+1];
__device__ int    g_cursor[NN];
__device__ int    g_bsum[SCAN_NB];
__device__ int    g_bar[4];               // spin-barrier counters (self-cleaning)
__device__ int    g_ssrc[EE];
__device__ int    g_sdst[EE];
__device__ int    g_oid[EE];

// ---------------- fused CSR build: hist -> scan -> scatter (one kernel) -----------
__global__ void __launch_bounds__(1024)
setup_fused(const int* __restrict__ src, const int* __restrict__ dst, int ne)
{
    __shared__ int sm[1024];
    int b = blockIdx.x, t = threadIdx.x;
    int nb = gridDim.x;
    int gid = b*1024 + t;
    int gsz = nb*1024;

    if (gid < NL*128) g_stats[gid] = 0.f;

    for (int i = gid; i < ne; i += gsz)
        atomicAdd(&g_hist[dst[i]], 1);

    __syncthreads();
    if (t == 0) {
        __threadfence();
        atomicAdd(&g_bar[0], 1);
        while (atomicAdd(&g_bar[0], 0) < nb) __nanosleep(64);
    }
    __syncthreads();

    int idx = gid;
    int v = (idx < SCAN_N) ? g_hist[idx] : 0;
    if (idx < SCAN_N) g_hist[idx] = 0;
    sm[t] = v;
    __syncthreads();
    for (int off = 1; off < 1024; off <<= 1) {
        int u = (t >= off) ? sm[t - off] : 0;
        __syncthreads();
        sm[t] += u;
        __syncthreads();
    }
    if (t == 1023) g_bsum[b] = sm[1023];
    __syncthreads();
    if (t == 0) {
        __threadfence();
        atomicAdd(&g_bar[1], 1);
        while (atomicAdd(&g_bar[1], 0) < nb) __nanosleep(64);
    }
    __syncthreads();
    int pre = 0;
    for (int i = 0; i < b; i++) pre += g_bsum[i];
    int excl = pre + sm[t] - v;
    if (idx < SCAN_N) {
        g_rowptr[idx] = excl;
        if (idx < NN) g_cursor[idx] = excl;
    }
    __syncthreads();
    if (t == 0) {
        __threadfence();
        atomicAdd(&g_bar[2], 1);
        while (atomicAdd(&g_bar[2], 0) < nb) __nanosleep(64);
    }
    __syncthreads();

    for (int i = gid; i < ne; i += gsz) {
        int d = dst[i];
        int pos = atomicAdd(&g_cursor[d], 1);
        g_ssrc[pos] = src[i];
        g_sdst[pos] = d;
        g_oid[pos]  = i;
    }

    __syncthreads();
    if (t == 0) {
        int done = atomicAdd(&g_bar[3], 1);
        if (done == nb - 1) {
            g_bar[0] = 0; g_bar[1] = 0; g_bar[2] = 0; g_bar[3] = 0;
            __threadfence();
        }
    }
}

// ------- gemm4: weights in REGISTERS (zero LDS); grid-stride over rows -----------
// Writes Ah, Bh (for ce_mma), Uh, and interleaved BV={Bh,Vh} (for agg2).
__global__ void __launch_bounds__(128)
gemm4_fused(const float* __restrict__ Aw, const float* __restrict__ Ab,
            const float* __restrict__ Bw, const float* __restrict__ Bb,
            const float* __restrict__ Uw, const float* __restrict__ Ub,
            const float* __restrict__ Vw, const float* __restrict__ Vb,
            const float* __restrict__ bng, const float* __restrict__ bnb,
            const float* __restrict__ x,
            const float* __restrict__ pw, const float* __restrict__ pb,
            int statSlot, int mode /*0=proj,1=update*/, int n)
{
    int lane = threadIdx.x & 31;
    float wA[32], wB[32], wU[32], wV[32];
    #pragma unroll
    for (int k = 0; k < 32; k++) {
        wA[k] = Aw[k*H + lane];
        wB[k] = Bw[k*H + lane];
        wU[k] = Uw[k*H + lane];
        wV[k] = Vw[k*H + lane];
    }
    float bA = Ab[lane], bB = Bb[lane], bU = Ub[lane], bV = Vb[lane];

    float mn = 0.f, sc = 0.f, bt = 0.f, pwl = 0.f, pbl = 0.f;
    if (mode == 1) {
        float inv = 1.0f / (float)n;
        float s1 = g_stats[statSlot*128 + lane];
        float s2 = g_stats[statSlot*128 + 32 + lane];
        mn = s1 * inv;
        float var = s2 * inv - mn * mn;
        sc = rsqrtf(var + 1e-5f) * bng[lane];
        bt = bnb[lane];
    } else {
        pwl = pw[lane]; pbl = pb[lane];
    }

    float2* bv2 = (float2*)g_BV;
    int warp0  = blockIdx.x * (blockDim.x >> 5) + (threadIdx.x >> 5);
    int stride = gridDim.x * (blockDim.x >> 5);
    for (int row = warp0; row < n; row += stride) {
        float hv;
        if (mode == 0) {
            hv = x[row] * pwl + pbl;
            g_h[row*H + lane] = hv;
        } else {
            hv = g_h[row*H + lane];
            float v = (g_hnew[row*H + lane] - mn) * sc + bt;
            hv += fmaxf(v, 0.f);
            g_h[row*H + lane] = hv;
        }
        float a = bA, b = bB, u = bU, v = bV;
        #pragma unroll
        for (int k = 0; k < 32; k++) {
            float hk = __shfl_sync(FULL, hv, k);
            a += hk * wA[k];
            b += hk * wB[k];
            u += hk * wU[k];
            v += hk * wV[k];
        }
        g_Ah[row*H + lane] = a;
        g_Bh[row*H + lane] = b;
        g_Uh[row*H + lane] = u;
        bv2[row*H + lane] = make_float2(b, v);
    }
}

// ---- tensor-core edge GEMM -> fp16 ce. N-split (2 x 16-col halves, unroll 1).
// eMode 1: project e from input (layer 0); store ce.
// eMode 2: reconstruct enew_{l-1} = Ah[d]+Bh[s]+ce_prev, apply e += relu(BN(enew));
//          write e back iff writeE. Must run BEFORE next layer's gemm4.
__global__ void __launch_bounds__(128)
ce_mma(const float* __restrict__ W, const float* __restrict__ bias,
       const float* __restrict__ bng, const float* __restrict__ bnb,
       const float* __restrict__ ein,
       const float* __restrict__ ew, const float* __restrict__ eb,
       int prevSlot, int eMode, int writeE, int ne, float inv_ne)
{
    __shared__ __half sWhi[32*32], sWlo[32*32];
    __shared__ __half sE[4][16*32];
    __shared__ float  sC[4][16*32];
    __shared__ float  sBias[32], sMn[32], sSc[32], sBt[32], sEw[32], sEb[32];

    int tid = threadIdx.x;
    for (int i = tid; i < 1024; i += 128) {
        float w = W[i];
        __half hi = __float2half_rn(w);
        sWhi[i] = hi;
        sWlo[i] = __float2half_rn(w - __half2float(hi));
    }
    if (tid < 32) {
        sBias[tid] = bias ? bias[tid] : 0.f;
        sMn[tid] = 0.f; sSc[tid] = 0.f; sBt[tid] = 0.f;
        sEw[tid] = 0.f; sEb[tid] = 0.f;
        if (eMode == 2) {
            float s1 = g_stats[prevSlot*128 + 64 + tid];
            float s2 = g_stats[prevSlot*128 + 96 + tid];
            float mean = s1 * inv_ne;
            float var  = s2 * inv_ne - mean * mean;
            sMn[tid] = mean;
            sSc[tid] = rsqrtf(var + 1e-5f) * bng[tid];
            sBt[tid] = bnb[tid];
        } else {
            sEw[tid] = ew[tid]; sEb[tid] = eb[tid];
        }
    }
    __syncthreads();

    int warp = tid >> 5, lane = tid & 31;

    __half2* e2  = (__half2*)g_e;
    __half2* ce2 = (__half2*)g_ce;
    int ntiles = (ne + 63) >> 6;

    for (int t = blockIdx.x; t < ntiles; t += gridDim.x) {
        int rbase = t*64 + warp*16;
        __half2* stage = (__half2*)sE[warp];
        #pragma unroll
        for (int i = 0; i < 8; i++) {
            int idx = i*32 + lane;
            int row = rbase + (idx >> 4);
            int ch  = idx & 15;
            if (row < ne) {
                size_t g = (size_t)row*16 + ch;
                if (eMode == 1) {
                    float xin = ein[g_oid[row]];
                    int c = ch*2;
                    __half2 nv = __floats2half2_rn(xin*sEw[c] + sEb[c],
                                                   xin*sEw[c+1] + sEb[c+1]);
                    e2[g] = nv;
                    stage[idx] = nv;
                } else {
                    int s = g_ssrc[row], d = g_sdst[row];
                    int c = ch*2;
                    float2 ah  = *(const float2*)(g_Ah + d*H + c);
                    float2 bhv = *(const float2*)(g_Bh + s*H + c);
                    float2 ce  = __half22float2(ce2[g]);
                    float enx = ah.x + bhv.x + ce.x;
                    float eny = ah.y + bhv.y + ce.y;
                    float2 f = __half22float2(e2[g]);
                    f.x += fmaxf((enx - sMn[c])   * sSc[c]   + sBt[c],   0.f);
                    f.y += fmaxf((eny - sMn[c+1]) * sSc[c+1] + sBt[c+1], 0.f);
                    __half2 nv = __floats2half2_rn(f.x, f.y);
                    if (writeE) e2[g] = nv;
                    stage[idx] = nv;
                }
            } else {
                stage[idx] = __floats2half2_rn(0.f, 0.f);
            }
        }
        __syncwarp();

        wmma::fragment<wmma::matrix_a, 16,16,16, __half, wmma::row_major> a0, a1;
        wmma::load_matrix_sync(a0, sE[warp],      32);
        wmma::load_matrix_sync(a1, sE[warp] + 16, 32);

        // N-split: 16 output columns at a time; only 4 B-frags + 1 acc live.
        #pragma unroll 1
        for (int nh = 0; nh < 2; nh++) {
            wmma::fragment<wmma::matrix_b, 16,16,16, __half, wmma::row_major> fbh0, fbh1, fbl0, fbl1;
            wmma::load_matrix_sync(fbh0, sWhi + nh*16,           32);
            wmma::load_matrix_sync(fbh1, sWhi + 16*32 + nh*16,   32);
            wmma::load_matrix_sync(fbl0, sWlo + nh*16,           32);
            wmma::load_matrix_sync(fbl1, sWlo + 16*32 + nh*16,   32);

            wmma::fragment<wmma::accumulator, 16,16,16, float> acc;
            wmma::fill_fragment(acc, 0.f);
            wmma::mma_sync(acc, a0, fbh0, acc);
            wmma::mma_sync(acc, a1, fbh1, acc);
            wmma::mma_sync(acc, a0, fbl0, acc);
            wmma::mma_sync(acc, a1, fbl1, acc);

            wmma::store_matrix_sync(sC[warp] + nh*16, acc, 32, wmma::mem_row_major);
        }
        __syncwarp();

        #pragma unroll
        for (int r = 0; r < 16; r++) {
            int row = rbase + r;
            if (row < ne)
                g_ce[(size_t)row*32 + lane] =
                    __float2half_rn(sC[warp][r*32 + lane] + sBias[lane]);
        }
        __syncwarp();
    }
}

// ---- aggregation: warp per node; one float2 BV gather per edge -------------------
__global__ void agg2(int curSlot, int n)
{
    int lane = threadIdx.x & 31;

    __shared__ float sE[32], qE[32], sH[32], qH[32];
    if (threadIdx.x < 32) {
        sE[threadIdx.x] = 0.f; qE[threadIdx.x] = 0.f;
        sH[threadIdx.x] = 0.f; qH[threadIdx.x] = 0.f;
    }
    __syncthreads();

    const float2* bv2 = (const float2*)g_BV;
    float ls = 0.f, lq = 0.f, hs = 0.f, hq = 0.f;
    int d = blockIdx.x * (blockDim.x >> 5) + (threadIdx.x >> 5);
    if (d < n) {
        int beg = g_rowptr[d], end = g_rowptr[d+1];
        float ah = g_Ah[d*H + lane];
        float uh = g_Uh[d*H + lane];
        float num = 0.f, den = 0.f;
        int i = beg;
        for (; i + 3 < end; i += 4) {
            int    s[4];
            float  ce[4];
            float2 bv[4];
            #pragma unroll
            for (int j = 0; j < 4; j++) s[j] = g_ssrc[i+j];
            #pragma unroll
            for (int j = 0; j < 4; j++) ce[j] = __half2float(g_ce[(size_t)(i+j)*H + lane]);
            #pragma unroll
            for (int j = 0; j < 4; j++) bv[j] = bv2[s[j]*H + lane];
            #pragma unroll
            for (int j = 0; j < 4; j++) {
                float en = ah + bv[j].x + ce[j];
                ls += en; lq += en * en;
                float sg = 1.0f / (1.0f + __expf(-en));
                num += sg * bv[j].y;
                den += sg;
            }
        }
        for (; i < end; i++) {
            int s0 = g_ssrc[i];
            float2 bv = bv2[s0*H + lane];
            float en = ah + bv.x + __half2float(g_ce[(size_t)i*H + lane]);
            ls += en; lq += en * en;
            float sg0 = 1.0f / (1.0f + __expf(-en));
            num += sg0 * bv.y;
            den += sg0;
        }
        float hn = uh + num / (den + 1e-6f);
        g_hnew[d*H + lane] = hn;
        hs += hn; hq += hn * hn;
    }
    atomicAdd(&sH[lane], hs); atomicAdd(&qH[lane], hq);
    atomicAdd(&sE[lane], ls); atomicAdd(&qE[lane], lq);
    __syncthreads();
    if (threadIdx.x < 32) {
        atomicAdd(&g_stats[curSlot*128 + threadIdx.x],      sH[threadIdx.x]);
        atomicAdd(&g_stats[curSlot*128 + 32 + threadIdx.x], qH[threadIdx.x]);
        atomicAdd(&g_stats[curSlot*128 + 64 + threadIdx.x], sE[threadIdx.x]);
        atomicAdd(&g_stats[curSlot*128 + 96 + threadIdx.x], qE[threadIdx.x]);
    }
}

// ---- score pre-pass: final h-update fused; hid_src -> g_Ah, hid_dst -> g_Bh ------
// (runs AFTER the final ce_mma, which needs the old Ah/Bh)
__global__ void __launch_bounds__(128)
score_gemm2(const float* __restrict__ W1, const float* __restrict__ b1,
            const float* __restrict__ bng, const float* __restrict__ bnb,
            int statSlot, int n)
{
    int lane = threadIdx.x & 31;
    float ws[32], wd[32];
    #pragma unroll
    for (int k = 0; k < 32; k++) {
        ws[k] = W1[k*32 + lane];
        wd[k] = W1[(32 + k)*32 + lane];
    }
    float bb = b1[lane];
    float inv = 1.0f / (float)n;
    float s1 = g_stats[statSlot*128 + lane];
    float s2 = g_stats[statSlot*128 + 32 + lane];
    float mn = s1 * inv;
    float var = s2 * inv - mn * mn;
    float sc = rsqrtf(var + 1e-5f) * bng[lane];
    float bt = bnb[lane];

    int warp0  = blockIdx.x * (blockDim.x >> 5) + (threadIdx.x >> 5);
    int stride = gridDim.x * (blockDim.x >> 5);
    for (int row = warp0; row < n; row += stride) {
        float hv = g_h[row*H + lane];
        hv += fmaxf((g_hnew[row*H + lane] - mn) * sc + bt, 0.f);
        float a = bb, c = 0.f;
        #pragma unroll
        for (int k = 0; k < 32; k++) {
            float hk = __shfl_sync(FULL, hv, k);
            a += hk * ws[k];
            c += hk * wd[k];
        }
        g_Ah[row*H + lane] = a;
        g_Bh[row*H + lane] = c;
    }
}

// ---- score: hid = relu(hid_s + hid_d + hid_e); out = hid @ W2 + b2 ---------------
__global__ void score_final(const float* __restrict__ W2, const float* __restrict__ b2,
                            float* __restrict__ out, int ne)
{
    int lane = threadIdx.x & 31;
    float w2 = W2[lane];
    float bb2 = b2[0];

    int i = blockIdx.x * (blockDim.x >> 5) + (threadIdx.x >> 5);
    if (i >= ne) return;
    int s = g_ssrc[i], d = g_sdst[i], o = g_oid[i];
    float hid = g_Ah[s*H + lane] + g_Bh[d*H + lane]
              + __half2float(g_ce[(size_t)i*H + lane]);
    hid = fmaxf(hid, 0.f);
    float p = hid * w2;
    #pragma unroll
    for (int off = 16; off > 0; off >>= 1)
        p += __shfl_xor_sync(FULL, p, off);
    if (lane == 0) out[o] = p + bb2;
}

// ==================================================================================
extern "C" void kernel_launch(void* const* d_in, const int* in_sizes, int n_in,
                              void* d_out, int out_size)
{
    const float* x    = (const float*)d_in[0];
    const float* ein  = (const float*)d_in[1];
    const int*   eidx = (const int*)  d_in[2];
    const float* pe_w = (const float*)d_in[3];
    const float* pe_b = (const float*)d_in[4];
    const float* ed_w = (const float*)d_in[5];
    const float* ed_b = (const float*)d_in[6];
    const float* A_w  = (const float*)d_in[7];
    const float* A_b  = (const float*)d_in[8];
    const float* B_w  = (const float*)d_in[9];
    const float* B_b  = (const float*)d_in[10];
    const float* C_w  = (const float*)d_in[11];
    const float* C_b  = (const float*)d_in[12];
    const float* U_w  = (const float*)d_in[13];
    const float* U_b  = (const float*)d_in[14];
    const float* V_w  = (const float*)d_in[15];
    const float* V_b  = (const float*)d_in[16];
    const float* bnhg = (const float*)d_in[17];
    const float* bnhb = (const float*)d_in[18];
    const float* bneg = (const float*)d_in[19];
    const float* bneb = (const float*)d_in[20];
    const float* W1_w = (const float*)d_in[21];
    const float* W1_b = (const float*)d_in[22];
    const float* W2_w = (const float*)d_in[23];
    const float* W2_b = (const float*)d_in[24];
    float* out = (float*)d_out;

    const int n  = in_sizes[0];
    const int ne = in_sizes[1];
    const int* src = eidx;
    const int* dst = eidx + ne;
    const float inv_ne = 1.0f / (float)ne;

    const int TB = 256;
    const int WPB = TB / 32;
    const int G_NODE_W = (n  + WPB - 1) / WPB;
    const int G_EDGE_W = (ne + WPB - 1) / WPB;
    const int G_MMA = 1480;
    const int G_G4  = 1480;

    // ---- fused CSR build: 1 launch ----
    setup_fused<<<SCAN_NB, 1024>>>(src, dst, ne);

    for (int l = 0; l < NL; l++) {
        // ce_mma BEFORE gemm4: eMode 2 reconstructs enew_{l-1} from old Ah/Bh.
        ce_mma<<<G_MMA, 128>>>(C_w + l*H*H, C_b + l*H,
                               bneg + (l-1)*H, bneb + (l-1)*H,
                               ein, ed_w, ed_b,
                               l-1, l == 0 ? 1 : 2, /*writeE=*/1, ne, inv_ne);

        gemm4_fused<<<G_G4, 128>>>(A_w + l*H*H, A_b + l*H,
                                   B_w + l*H*H, B_b + l*H,
                                   U_w + l*H*H, U_b + l*H,
                                   V_w + l*H*H, V_b + l*H,
                                   bnhg + (l-1)*H, bnhb + (l-1)*H,
                                   x, pe_w, pe_b,
                                   l-1, l == 0 ? 0 : 1, n);

        agg2<<<G_NODE_W, TB>>>(l, n);      // launch #4 on l=0 -> profiled
    }

    // final edge term BEFORE score_gemm2 (needs Ah_3/Bh_3 for enew reconstruction)
    ce_mma<<<G_MMA, 128>>>(W1_w + 64*32, (const float*)nullptr,
                           bneg + (NL-1)*H, bneb + (NL-1)*H,
                           (const float*)nullptr, (const float*)nullptr,
                           (const float*)nullptr,
                           NL-1, /*eMode=*/2, /*writeE=*/0, ne, inv_ne);
    score_gemm2<<<G_G4, 128>>>(W1_w, W1_b,
                               bnhg + (NL-1)*H, bnhb + (NL-1)*H, NL-1, n);
    score_final<<<G_EDGE_W, TB>>>(W2_w, W2_b, out, ne);
}

// round 15
// speedup vs baseline: 1.3750x; 1.0132x over previous
#include <cuda_runtime.h>
#include <cuda_fp16.h>
#include <mma.h>
#include <math.h>

using namespace nvcuda;

#define NN 100000
#define EE 800000
#define H  32
#define NL 4
#define FULL 0xffffffffu
#define SCAN_N   (NN + 1)
#define SCAN_NB  ((SCAN_N + 1023) / 1024)

// ---------------- scratch ---------------------------------------------------------
__device__ float  g_h[NN*H];
__device__ float  g_hnew[NN*H];
__device__ float  g_Ah[NN*H];
__device__ float  g_Bh[NN*H];      // used only by score pre-pass outputs
__device__ float  g_Uh[NN*H];
__device__ float  g_BV[NN*H*2];    // interleaved {Bh,Vh} per (row,lane) for agg2 gathers
__device__ __half g_e[EE*H];       // e_l (dst-sorted)
__device__ __half g_ce[EE*H];      // ce_mma writes Ce; agg2 overwrites with enew (handoff)
// stats slots: per layer l: [l*128 + 0:64) h sum/sq, [l*128+64:128) e sum/sq
__device__ float  g_stats[NL*128];
__device__ int    g_hist[SCAN_NB*1024];   // zero at load; setup re-zeros (leave-clean)
__device__ int    g_rowptr[NN+1];
__device__ int    g_cursor[NN];
__device__ int    g_bsum[SCAN_NB];
__device__ int    g_bar[4];               // spin-barrier counters (self-cleaning)
__device__ int    g_ssrc[EE];
__device__ int    g_sdst[EE];
__device__ int    g_oid[EE];

// ---------------- fused CSR build: hist -> scan -> scatter (one kernel) -----------
__global__ void __launch_bounds__(1024)
setup_fused(const int* __restrict__ src, const int* __restrict__ dst, int ne)
{
    __shared__ int sm[1024];
    int b = blockIdx.x, t = threadIdx.x;
    int nb = gridDim.x;
    int gid = b*1024 + t;
    int gsz = nb*1024;

    if (gid < NL*128) g_stats[gid] = 0.f;

    for (int i = gid; i < ne; i += gsz)
        atomicAdd(&g_hist[dst[i]], 1);

    __syncthreads();
    if (t == 0) {
        __threadfence();
        atomicAdd(&g_bar[0], 1);
        while (atomicAdd(&g_bar[0], 0) < nb) __nanosleep(64);
    }
    __syncthreads();

    int idx = gid;
    int v = (idx < SCAN_N) ? g_hist[idx] : 0;
    if (idx < SCAN_N) g_hist[idx] = 0;
    sm[t] = v;
    __syncthreads();
    for (int off = 1; off < 1024; off <<= 1) {
        int u = (t >= off) ? sm[t - off] : 0;
        __syncthreads();
        sm[t] += u;
        __syncthreads();
    }
    if (t == 1023) g_bsum[b] = sm[1023];
    __syncthreads();
    if (t == 0) {
        __threadfence();
        atomicAdd(&g_bar[1], 1);
        while (atomicAdd(&g_bar[1], 0) < nb) __nanosleep(64);
    }
    __syncthreads();
    int pre = 0;
    for (int i = 0; i < b; i++) pre += g_bsum[i];
    int excl = pre + sm[t] - v;
    if (idx < SCAN_N) {
        g_rowptr[idx] = excl;
        if (idx < NN) g_cursor[idx] = excl;
    }
    __syncthreads();
    if (t == 0) {
        __threadfence();
        atomicAdd(&g_bar[2], 1);
        while (atomicAdd(&g_bar[2], 0) < nb) __nanosleep(64);
    }
    __syncthreads();

    for (int i = gid; i < ne; i += gsz) {
        int d = dst[i];
        int pos = atomicAdd(&g_cursor[d], 1);
        g_ssrc[pos] = src[i];
        g_sdst[pos] = d;
        g_oid[pos]  = i;
    }

    __syncthreads();
    if (t == 0) {
        int done = atomicAdd(&g_bar[3], 1);
        if (done == nb - 1) {
            g_bar[0] = 0; g_bar[1] = 0; g_bar[2] = 0; g_bar[3] = 0;
            __threadfence();
        }
    }
}

// ------- gemm4: weights in REGISTERS (zero LDS); grid-stride over rows -----------
// Writes Ah, Uh, and interleaved BV={Bh,Vh}. (Separate Bh store is dead: ce_mma
// no longer gathers Bh; agg2 uses BV.)
__global__ void __launch_bounds__(128)
gemm4_fused(const float* __restrict__ Aw, const float* __restrict__ Ab,
            const float* __restrict__ Bw, const float* __restrict__ Bb,
            const float* __restrict__ Uw, const float* __restrict__ Ub,
            const float* __restrict__ Vw, const float* __restrict__ Vb,
            const float* __restrict__ bng, const float* __restrict__ bnb,
            const float* __restrict__ x,
            const float* __restrict__ pw, const float* __restrict__ pb,
            int statSlot, int mode /*0=proj,1=update*/, int n)
{
    int lane = threadIdx.x & 31;
    float wA[32], wB[32], wU[32], wV[32];
    #pragma unroll
    for (int k = 0; k < 32; k++) {
        wA[k] = Aw[k*H + lane];
        wB[k] = Bw[k*H + lane];
        wU[k] = Uw[k*H + lane];
        wV[k] = Vw[k*H + lane];
    }
    float bA = Ab[lane], bB = Bb[lane], bU = Ub[lane], bV = Vb[lane];

    float mn = 0.f, sc = 0.f, bt = 0.f, pwl = 0.f, pbl = 0.f;
    if (mode == 1) {
        float inv = 1.0f / (float)n;
        float s1 = g_stats[statSlot*128 + lane];
        float s2 = g_stats[statSlot*128 + 32 + lane];
        mn = s1 * inv;
        float var = s2 * inv - mn * mn;
        sc = rsqrtf(var + 1e-5f) * bng[lane];
        bt = bnb[lane];
    } else {
        pwl = pw[lane]; pbl = pb[lane];
    }

    float2* bv2 = (float2*)g_BV;
    int warp0  = blockIdx.x * (blockDim.x >> 5) + (threadIdx.x >> 5);
    int stride = gridDim.x * (blockDim.x >> 5);
    for (int row = warp0; row < n; row += stride) {
        float hv;
        if (mode == 0) {
            hv = x[row] * pwl + pbl;
            g_h[row*H + lane] = hv;
        } else {
            hv = g_h[row*H + lane];
            float v = (g_hnew[row*H + lane] - mn) * sc + bt;
            hv += fmaxf(v, 0.f);
            g_h[row*H + lane] = hv;
        }
        float a = bA, b = bB, u = bU, v = bV;
        #pragma unroll
        for (int k = 0; k < 32; k++) {
            float hk = __shfl_sync(FULL, hv, k);
            a += hk * wA[k];
            b += hk * wB[k];
            u += hk * wU[k];
            v += hk * wV[k];
        }
        g_Ah[row*H + lane] = a;
        g_Uh[row*H + lane] = u;
        bv2[row*H + lane] = make_float2(b, v);
    }
}

// ---- tensor-core edge GEMM -> fp16 ce. N-split (2 x 16-col halves, unroll 1).
// eMode 1: project e from input (layer 0); store ce.
// eMode 2: g_ce currently holds enew_{l-1} (written by agg2). Staging just reads
//          it: e += relu(BN(enew)); write e back iff writeE; then GEMM overwrites
//          g_ce with this layer's Ce. NO gathers, NO index loads.
__global__ void __launch_bounds__(128)
ce_mma(const float* __restrict__ W, const float* __restrict__ bias,
       const float* __restrict__ bng, const float* __restrict__ bnb,
       const float* __restrict__ ein,
       const float* __restrict__ ew, const float* __restrict__ eb,
       int prevSlot, int eMode, int writeE, int ne, float inv_ne)
{
    __shared__ __half sWhi[32*32], sWlo[32*32];
    __shared__ __half sE[4][16*32];
    __shared__ float  sC[4][16*32];
    __shared__ float  sBias[32], sMn[32], sSc[32], sBt[32], sEw[32], sEb[32];

    int tid = threadIdx.x;
    for (int i = tid; i < 1024; i += 128) {
        float w = W[i];
        __half hi = __float2half_rn(w);
        sWhi[i] = hi;
        sWlo[i] = __float2half_rn(w - __half2float(hi));
    }
    if (tid < 32) {
        sBias[tid] = bias ? bias[tid] : 0.f;
        sMn[tid] = 0.f; sSc[tid] = 0.f; sBt[tid] = 0.f;
        sEw[tid] = 0.f; sEb[tid] = 0.f;
        if (eMode == 2) {
            float s1 = g_stats[prevSlot*128 + 64 + tid];
            float s2 = g_stats[prevSlot*128 + 96 + tid];
            float mean = s1 * inv_ne;
            float var  = s2 * inv_ne - mean * mean;
            sMn[tid] = mean;
            sSc[tid] = rsqrtf(var + 1e-5f) * bng[tid];
            sBt[tid] = bnb[tid];
        } else {
            sEw[tid] = ew[tid]; sEb[tid] = eb[tid];
        }
    }
    __syncthreads();

    int warp = tid >> 5, lane = tid & 31;

    __half2* e2  = (__half2*)g_e;
    __half2* ce2 = (__half2*)g_ce;
    int ntiles = (ne + 63) >> 6;

    for (int t = blockIdx.x; t < ntiles; t += gridDim.x) {
        int rbase = t*64 + warp*16;
        __half2* stage = (__half2*)sE[warp];
        #pragma unroll
        for (int i = 0; i < 8; i++) {
            int idx = i*32 + lane;
            int row = rbase + (idx >> 4);
            int ch  = idx & 15;
            if (row < ne) {
                size_t g = (size_t)row*16 + ch;
                if (eMode == 1) {
                    float xin = ein[g_oid[row]];
                    int c = ch*2;
                    __half2 nv = __floats2half2_rn(xin*sEw[c] + sEb[c],
                                                   xin*sEw[c+1] + sEb[c+1]);
                    e2[g] = nv;
                    stage[idx] = nv;
                } else {
                    int c = ch*2;
                    float2 en = __half22float2(ce2[g]);   // enew_{l-1} via agg2 handoff
                    float2 f  = __half22float2(e2[g]);
                    f.x += fmaxf((en.x - sMn[c])   * sSc[c]   + sBt[c],   0.f);
                    f.y += fmaxf((en.y - sMn[c+1]) * sSc[c+1] + sBt[c+1], 0.f);
                    __half2 nv = __floats2half2_rn(f.x, f.y);
                    if (writeE) e2[g] = nv;
                    stage[idx] = nv;
                }
            } else {
                stage[idx] = __floats2half2_rn(0.f, 0.f);
            }
        }
        __syncwarp();

        wmma::fragment<wmma::matrix_a, 16,16,16, __half, wmma::row_major> a0, a1;
        wmma::load_matrix_sync(a0, sE[warp],      32);
        wmma::load_matrix_sync(a1, sE[warp] + 16, 32);

        // N-split: 16 output columns at a time; only 4 B-frags + 1 acc live.
        #pragma unroll 1
        for (int nh = 0; nh < 2; nh++) {
            wmma::fragment<wmma::matrix_b, 16,16,16, __half, wmma::row_major> fbh0, fbh1, fbl0, fbl1;
            wmma::load_matrix_sync(fbh0, sWhi + nh*16,           32);
            wmma::load_matrix_sync(fbh1, sWhi + 16*32 + nh*16,   32);
            wmma::load_matrix_sync(fbl0, sWlo + nh*16,           32);
            wmma::load_matrix_sync(fbl1, sWlo + 16*32 + nh*16,   32);

            wmma::fragment<wmma::accumulator, 16,16,16, float> acc;
            wmma::fill_fragment(acc, 0.f);
            wmma::mma_sync(acc, a0, fbh0, acc);
            wmma::mma_sync(acc, a1, fbh1, acc);
            wmma::mma_sync(acc, a0, fbl0, acc);
            wmma::mma_sync(acc, a1, fbl1, acc);

            wmma::store_matrix_sync(sC[warp] + nh*16, acc, 32, wmma::mem_row_major);
        }
        __syncwarp();

        #pragma unroll
        for (int r = 0; r < 16; r++) {
            int row = rbase + r;
            if (row < ne)
                g_ce[(size_t)row*32 + lane] =
                    __float2half_rn(sC[warp][r*32 + lane] + sBias[lane]);
        }
        __syncwarp();
    }
}

// ---- aggregation: warp per node; writes enew back into g_ce (handoff) ------------
__global__ void agg2(int curSlot, int n)
{
    int lane = threadIdx.x & 31;

    __shared__ float sE[32], qE[32], sH[32], qH[32];
    if (threadIdx.x < 32) {
        sE[threadIdx.x] = 0.f; qE[threadIdx.x] = 0.f;
        sH[threadIdx.x] = 0.f; qH[threadIdx.x] = 0.f;
    }
    __syncthreads();

    const float2* bv2 = (const float2*)g_BV;
    float ls = 0.f, lq = 0.f, hs = 0.f, hq = 0.f;
    int d = blockIdx.x * (blockDim.x >> 5) + (threadIdx.x >> 5);
    if (d < n) {
        int beg = g_rowptr[d], end = g_rowptr[d+1];
        float ah = g_Ah[d*H + lane];
        float uh = g_Uh[d*H + lane];
        float num = 0.f, den = 0.f;
        int i = beg;
        for (; i + 3 < end; i += 4) {
            int    s[4];
            float  ce[4];
            float2 bv[4];
            #pragma unroll
            for (int j = 0; j < 4; j++) s[j] = g_ssrc[i+j];
            #pragma unroll
            for (int j = 0; j < 4; j++) ce[j] = __half2float(g_ce[(size_t)(i+j)*H + lane]);
            #pragma unroll
            for (int j = 0; j < 4; j++) bv[j] = bv2[s[j]*H + lane];
            #pragma unroll
            for (int j = 0; j < 4; j++) {
                float en = ah + bv[j].x + ce[j];
                g_ce[(size_t)(i+j)*H + lane] = __float2half_rn(en);  // handoff: enew
                ls += en; lq += en * en;
                float sg = 1.0f / (1.0f + __expf(-en));
                num += sg * bv[j].y;
                den += sg;
            }
        }
        for (; i < end; i++) {
            int s0 = g_ssrc[i];
            float2 bv = bv2[s0*H + lane];
            float en = ah + bv.x + __half2float(g_ce[(size_t)i*H + lane]);
            g_ce[(size_t)i*H + lane] = __float2half_rn(en);          // handoff: enew
            ls += en; lq += en * en;
            float sg0 = 1.0f / (1.0f + __expf(-en));
            num += sg0 * bv.y;
            den += sg0;
        }
        float hn = uh + num / (den + 1e-6f);
        g_hnew[d*H + lane] = hn;
        hs += hn; hq += hn * hn;
    }
    atomicAdd(&sH[lane], hs); atomicAdd(&qH[lane], hq);
    atomicAdd(&sE[lane], ls); atomicAdd(&qE[lane], lq);
    __syncthreads();
    if (threadIdx.x < 32) {
        atomicAdd(&g_stats[curSlot*128 + threadIdx.x],      sH[threadIdx.x]);
        atomicAdd(&g_stats[curSlot*128 + 32 + threadIdx.x], qH[threadIdx.x]);
        atomicAdd(&g_stats[curSlot*128 + 64 + threadIdx.x], sE[threadIdx.x]);
        atomicAdd(&g_stats[curSlot*128 + 96 + threadIdx.x], qE[threadIdx.x]);
    }
}

// ---- score pre-pass: final h-update fused; hid_src -> g_Ah, hid_dst -> g_Bh ------
__global__ void __launch_bounds__(128)
score_gemm2(const float* __restrict__ W1, const float* __restrict__ b1,
            const float* __restrict__ bng, const float* __restrict__ bnb,
            int statSlot, int n)
{
    int lane = threadIdx.x & 31;
    float ws[32], wd[32];
    #pragma unroll
    for (int k = 0; k < 32; k++) {
        ws[k] = W1[k*32 + lane];
        wd[k] = W1[(32 + k)*32 + lane];
    }
    float bb = b1[lane];
    float inv = 1.0f / (float)n;
    float s1 = g_stats[statSlot*128 + lane];
    float s2 = g_stats[statSlot*128 + 32 + lane];
    float mn = s1 * inv;
    float var = s2 * inv - mn * mn;
    float sc = rsqrtf(var + 1e-5f) * bng[lane];
    float bt = bnb[lane];

    int warp0  = blockIdx.x * (blockDim.x >> 5) + (threadIdx.x >> 5);
    int stride = gridDim.x * (blockDim.x >> 5);
    for (int row = warp0; row < n; row += stride) {
        float hv = g_h[row*H + lane];
        hv += fmaxf((g_hnew[row*H + lane] - mn) * sc + bt, 0.f);
        float a = bb, c = 0.f;
        #pragma unroll
        for (int k = 0; k < 32; k++) {
            float hk = __shfl_sync(FULL, hv, k);
            a += hk * ws[k];
            c += hk * wd[k];
        }
        g_Ah[row*H + lane] = a;
        g_Bh[row*H + lane] = c;
    }
}

// ---- score: hid = relu(hid_s + hid_d + hid_e); out = hid @ W2 + b2 ---------------
__global__ void score_final(const float* __restrict__ W2, const float* __restrict__ b2,
                            float* __restrict__ out, int ne)
{
    int lane = threadIdx.x & 31;
    float w2 = W2[lane];
    float bb2 = b2[0];

    int i = blockIdx.x * (blockDim.x >> 5) + (threadIdx.x >> 5);
    if (i >= ne) return;
    int s = g_ssrc[i], d = g_sdst[i], o = g_oid[i];
    float hid = g_Ah[s*H + lane] + g_Bh[d*H + lane]
              + __half2float(g_ce[(size_t)i*H + lane]);
    hid = fmaxf(hid, 0.f);
    float p = hid * w2;
    #pragma unroll
    for (int off = 16; off > 0; off >>= 1)
        p += __shfl_xor_sync(FULL, p, off);
    if (lane == 0) out[o] = p + bb2;
}

// ==================================================================================
extern "C" void kernel_launch(void* const* d_in, const int* in_sizes, int n_in,
                              void* d_out, int out_size)
{
    const float* x    = (const float*)d_in[0];
    const float* ein  = (const float*)d_in[1];
    const int*   eidx = (const int*)  d_in[2];
    const float* pe_w = (const float*)d_in[3];
    const float* pe_b = (const float*)d_in[4];
    const float* ed_w = (const float*)d_in[5];
    const float* ed_b = (const float*)d_in[6];
    const float* A_w  = (const float*)d_in[7];
    const float* A_b  = (const float*)d_in[8];
    const float* B_w  = (const float*)d_in[9];
    const float* B_b  = (const float*)d_in[10];
    const float* C_w  = (const float*)d_in[11];
    const float* C_b  = (const float*)d_in[12];
    const float* U_w  = (const float*)d_in[13];
    const float* U_b  = (const float*)d_in[14];
    const float* V_w  = (const float*)d_in[15];
    const float* V_b  = (const float*)d_in[16];
    const float* bnhg = (const float*)d_in[17];
    const float* bnhb = (const float*)d_in[18];
    const float* bneg = (const float*)d_in[19];
    const float* bneb = (const float*)d_in[20];
    const float* W1_w = (const float*)d_in[21];
    const float* W1_b = (const float*)d_in[22];
    const float* W2_w = (const float*)d_in[23];
    const float* W2_b = (const float*)d_in[24];
    float* out = (float*)d_out;

    const int n  = in_sizes[0];
    const int ne = in_sizes[1];
    const int* src = eidx;
    const int* dst = eidx + ne;
    const float inv_ne = 1.0f / (float)ne;

    const int TB = 256;
    const int WPB = TB / 32;
    const int G_NODE_W = (n  + WPB - 1) / WPB;
    const int G_EDGE_W = (ne + WPB - 1) / WPB;
    const int G_MMA = 1480;
    const int G_G4  = 1480;

    // ---- fused CSR build: 1 launch ----
    setup_fused<<<SCAN_NB, 1024>>>(src, dst, ne);

    for (int l = 0; l < NL; l++) {
        // eMode 2 reads enew_{l-1} straight from g_ce (agg2 handoff); no gathers.
        ce_mma<<<G_MMA, 128>>>(C_w + l*H*H, C_b + l*H,
                               bneg + (l-1)*H, bneb + (l-1)*H,
                               ein, ed_w, ed_b,
                               l-1, l == 0 ? 1 : 2, /*writeE=*/1, ne, inv_ne);

        gemm4_fused<<<G_G4, 128>>>(A_w + l*H*H, A_b + l*H,
                                   B_w + l*H*H, B_b + l*H,
                                   U_w + l*H*H, U_b + l*H,
                                   V_w + l*H*H, V_b + l*H,
                                   bnhg + (l-1)*H, bnhb + (l-1)*H,
                                   x, pe_w, pe_b,
                                   l-1, l == 0 ? 0 : 1, n);

        agg2<<<G_NODE_W, TB>>>(l, n);      // launch #4 on l=0 -> profiled
    }

    // final edge term: reads enew_3 from g_ce handoff; GEMM with W1[64:96] -> hid_e
    ce_mma<<<G_MMA, 128>>>(W1_w + 64*32, (const float*)nullptr,
                           bneg + (NL-1)*H, bneb + (NL-1)*H,
                           (const float*)nullptr, (const float*)nullptr,
                           (const float*)nullptr,
                           NL-1, /*eMode=*/2, /*writeE=*/0, ne, inv_ne);
    score_gemm2<<<G_G4, 128>>>(W1_w, W1_b,
                               bnhg + (NL-1)*H, bnhb + (NL-1)*H, NL-1, n);
    score_final<<<G_EDGE_W, TB>>>(W2_w, W2_b, out, ne);
}

// round 16
// speedup vs baseline: 1.3962x; 1.0154x over previous
#include <cuda_runtime.h>
#include <cuda_fp16.h>
#include <mma.h>
#include <math.h>

using namespace nvcuda;

#define NN 100000
#define EE 800000
#define H  32
#define NL 4
#define FULL 0xffffffffu
#define SCAN_N   (NN + 1)
#define SCAN_NB  ((SCAN_N + 1023) / 1024)

// ---------------- scratch ---------------------------------------------------------
__device__ float  g_h[NN*H];
__device__ float  g_hnew[NN*H];
__device__ float  g_Ah[NN*H];
__device__ float  g_Bh[NN*H];      // used only by score pre-pass outputs
__device__ float  g_Uh[NN*H];
__device__ float  g_BV[NN*H*2];    // interleaved {Bh,Vh} per (row,lane) for agg2 gathers
__device__ __half g_e[EE*H];       // e_l (dst-sorted)
__device__ __half g_ce[EE*H];      // ce_mma writes Ce; agg2 overwrites with enew (handoff)
// stats slots: per layer l: [l*128 + 0:64) h sum/sq, [l*128+64:128) e sum/sq
__device__ float  g_stats[NL*128];
__device__ int    g_hist[SCAN_NB*1024];   // zero at load; setup re-zeros (leave-clean)
__device__ int    g_rowptr[NN+1];
__device__ int    g_cursor[NN];
__device__ int    g_bsum[SCAN_NB];
__device__ int    g_bar[4];               // spin-barrier counters (self-cleaning)
__device__ int    g_ssrc[EE];
__device__ int    g_sdst[EE];
__device__ int    g_oid[EE];

// ---------------- fused CSR build: hist -> scan -> scatter (one kernel) -----------
__global__ void __launch_bounds__(1024)
setup_fused(const int* __restrict__ src, const int* __restrict__ dst, int ne)
{
    __shared__ int sm[1024];
    int b = blockIdx.x, t = threadIdx.x;
    int nb = gridDim.x;
    int gid = b*1024 + t;
    int gsz = nb*1024;

    if (gid < NL*128) g_stats[gid] = 0.f;

    for (int i = gid; i < ne; i += gsz)
        atomicAdd(&g_hist[dst[i]], 1);

    __syncthreads();
    if (t == 0) {
        __threadfence();
        atomicAdd(&g_bar[0], 1);
        while (atomicAdd(&g_bar[0], 0) < nb) __nanosleep(64);
    }
    __syncthreads();

    int idx = gid;
    int v = (idx < SCAN_N) ? g_hist[idx] : 0;
    if (idx < SCAN_N) g_hist[idx] = 0;
    sm[t] = v;
    __syncthreads();
    for (int off = 1; off < 1024; off <<= 1) {
        int u = (t >= off) ? sm[t - off] : 0;
        __syncthreads();
        sm[t] += u;
        __syncthreads();
    }
    if (t == 1023) g_bsum[b] = sm[1023];
    __syncthreads();
    if (t == 0) {
        __threadfence();
        atomicAdd(&g_bar[1], 1);
        while (atomicAdd(&g_bar[1], 0) < nb) __nanosleep(64);
    }
    __syncthreads();
    int pre = 0;
    for (int i = 0; i < b; i++) pre += g_bsum[i];
    int excl = pre + sm[t] - v;
    if (idx < SCAN_N) {
        g_rowptr[idx] = excl;
        if (idx < NN) g_cursor[idx] = excl;
    }
    __syncthreads();
    if (t == 0) {
        __threadfence();
        atomicAdd(&g_bar[2], 1);
        while (atomicAdd(&g_bar[2], 0) < nb) __nanosleep(64);
    }
    __syncthreads();

    for (int i = gid; i < ne; i += gsz) {
        int d = dst[i];
        int pos = atomicAdd(&g_cursor[d], 1);
        g_ssrc[pos] = src[i];
        g_sdst[pos] = d;
        g_oid[pos]  = i;
    }

    __syncthreads();
    if (t == 0) {
        int done = atomicAdd(&g_bar[3], 1);
        if (done == nb - 1) {
            g_bar[0] = 0; g_bar[1] = 0; g_bar[2] = 0; g_bar[3] = 0;
            __threadfence();
        }
    }
}

// ------- gemm4: weights in REGISTERS (zero LDS); grid-stride over rows -----------
__global__ void __launch_bounds__(128)
gemm4_fused(const float* __restrict__ Aw, const float* __restrict__ Ab,
            const float* __restrict__ Bw, const float* __restrict__ Bb,
            const float* __restrict__ Uw, const float* __restrict__ Ub,
            const float* __restrict__ Vw, const float* __restrict__ Vb,
            const float* __restrict__ bng, const float* __restrict__ bnb,
            const float* __restrict__ x,
            const float* __restrict__ pw, const float* __restrict__ pb,
            int statSlot, int mode /*0=proj,1=update*/, int n)
{
    int lane = threadIdx.x & 31;
    float wA[32], wB[32], wU[32], wV[32];
    #pragma unroll
    for (int k = 0; k < 32; k++) {
        wA[k] = Aw[k*H + lane];
        wB[k] = Bw[k*H + lane];
        wU[k] = Uw[k*H + lane];
        wV[k] = Vw[k*H + lane];
    }
    float bA = Ab[lane], bB = Bb[lane], bU = Ub[lane], bV = Vb[lane];

    float mn = 0.f, sc = 0.f, bt = 0.f, pwl = 0.f, pbl = 0.f;
    if (mode == 1) {
        float inv = 1.0f / (float)n;
        float s1 = g_stats[statSlot*128 + lane];
        float s2 = g_stats[statSlot*128 + 32 + lane];
        mn = s1 * inv;
        float var = s2 * inv - mn * mn;
        sc = rsqrtf(var + 1e-5f) * bng[lane];
        bt = bnb[lane];
    } else {
        pwl = pw[lane]; pbl = pb[lane];
    }

    float2* bv2 = (float2*)g_BV;
    int warp0  = blockIdx.x * (blockDim.x >> 5) + (threadIdx.x >> 5);
    int stride = gridDim.x * (blockDim.x >> 5);
    for (int row = warp0; row < n; row += stride) {
        float hv;
        if (mode == 0) {
            hv = x[row] * pwl + pbl;
            g_h[row*H + lane] = hv;
        } else {
            hv = g_h[row*H + lane];
            float v = (g_hnew[row*H + lane] - mn) * sc + bt;
            hv += fmaxf(v, 0.f);
            g_h[row*H + lane] = hv;
        }
        float a = bA, b = bB, u = bU, v = bV;
        #pragma unroll
        for (int k = 0; k < 32; k++) {
            float hk = __shfl_sync(FULL, hv, k);
            a += hk * wA[k];
            b += hk * wB[k];
            u += hk * wU[k];
            v += hk * wV[k];
        }
        g_Ah[row*H + lane] = a;
        g_Uh[row*H + lane] = u;
        bv2[row*H + lane] = make_float2(b, v);
    }
}

// ---- tensor-core edge GEMM -> fp16 ce. N-split (2 x 16-col halves, unroll 1).
// eMode 1: project e from input (layer 0); store ce.
// eMode 2: g_ce holds enew_{l-1} (agg2 handoff): e += relu(BN(enew)); write e
//          iff writeE; GEMM overwrites g_ce with this layer's Ce. No gathers.
__global__ void __launch_bounds__(128)
ce_mma(const float* __restrict__ W, const float* __restrict__ bias,
       const float* __restrict__ bng, const float* __restrict__ bnb,
       const float* __restrict__ ein,
       const float* __restrict__ ew, const float* __restrict__ eb,
       int prevSlot, int eMode, int writeE, int ne, float inv_ne)
{
    __shared__ __half sWhi[32*32], sWlo[32*32];
    __shared__ __half sE[4][16*32];
    __shared__ float  sC[4][16*32];
    __shared__ float  sBias[32], sMn[32], sSc[32], sBt[32], sEw[32], sEb[32];

    int tid = threadIdx.x;
    for (int i = tid; i < 1024; i += 128) {
        float w = W[i];
        __half hi = __float2half_rn(w);
        sWhi[i] = hi;
        sWlo[i] = __float2half_rn(w - __half2float(hi));
    }
    if (tid < 32) {
        sBias[tid] = bias ? bias[tid] : 0.f;
        sMn[tid] = 0.f; sSc[tid] = 0.f; sBt[tid] = 0.f;
        sEw[tid] = 0.f; sEb[tid] = 0.f;
        if (eMode == 2) {
            float s1 = g_stats[prevSlot*128 + 64 + tid];
            float s2 = g_stats[prevSlot*128 + 96 + tid];
            float mean = s1 * inv_ne;
            float var  = s2 * inv_ne - mean * mean;
            sMn[tid] = mean;
            sSc[tid] = rsqrtf(var + 1e-5f) * bng[tid];
            sBt[tid] = bnb[tid];
        } else {
            sEw[tid] = ew[tid]; sEb[tid] = eb[tid];
        }
    }
    __syncthreads();

    int warp = tid >> 5, lane = tid & 31;

    __half2* e2  = (__half2*)g_e;
    __half2* ce2 = (__half2*)g_ce;
    int ntiles = (ne + 63) >> 6;

    for (int t = blockIdx.x; t < ntiles; t += gridDim.x) {
        int rbase = t*64 + warp*16;
        __half2* stage = (__half2*)sE[warp];
        #pragma unroll
        for (int i = 0; i < 8; i++) {
            int idx = i*32 + lane;
            int row = rbase + (idx >> 4);
            int ch  = idx & 15;
            if (row < ne) {
                size_t g = (size_t)row*16 + ch;
                if (eMode == 1) {
                    float xin = ein[g_oid[row]];
                    int c = ch*2;
                    __half2 nv = __floats2half2_rn(xin*sEw[c] + sEb[c],
                                                   xin*sEw[c+1] + sEb[c+1]);
                    e2[g] = nv;
                    stage[idx] = nv;
                } else {
                    int c = ch*2;
                    float2 en = __half22float2(ce2[g]);   // enew_{l-1} via handoff
                    float2 f  = __half22float2(e2[g]);
                    f.x += fmaxf((en.x - sMn[c])   * sSc[c]   + sBt[c],   0.f);
                    f.y += fmaxf((en.y - sMn[c+1]) * sSc[c+1] + sBt[c+1], 0.f);
                    __half2 nv = __floats2half2_rn(f.x, f.y);
                    if (writeE) e2[g] = nv;
                    stage[idx] = nv;
                }
            } else {
                stage[idx] = __floats2half2_rn(0.f, 0.f);
            }
        }
        __syncwarp();

        wmma::fragment<wmma::matrix_a, 16,16,16, __half, wmma::row_major> a0, a1;
        wmma::load_matrix_sync(a0, sE[warp],      32);
        wmma::load_matrix_sync(a1, sE[warp] + 16, 32);

        #pragma unroll 1
        for (int nh = 0; nh < 2; nh++) {
            wmma::fragment<wmma::matrix_b, 16,16,16, __half, wmma::row_major> fbh0, fbh1, fbl0, fbl1;
            wmma::load_matrix_sync(fbh0, sWhi + nh*16,           32);
            wmma::load_matrix_sync(fbh1, sWhi + 16*32 + nh*16,   32);
            wmma::load_matrix_sync(fbl0, sWlo + nh*16,           32);
            wmma::load_matrix_sync(fbl1, sWlo + 16*32 + nh*16,   32);

            wmma::fragment<wmma::accumulator, 16,16,16, float> acc;
            wmma::fill_fragment(acc, 0.f);
            wmma::mma_sync(acc, a0, fbh0, acc);
            wmma::mma_sync(acc, a1, fbh1, acc);
            wmma::mma_sync(acc, a0, fbl0, acc);
            wmma::mma_sync(acc, a1, fbl1, acc);

            wmma::store_matrix_sync(sC[warp] + nh*16, acc, 32, wmma::mem_row_major);
        }
        __syncwarp();

        #pragma unroll
        for (int r = 0; r < 16; r++) {
            int row = rbase + r;
            if (row < ne)
                g_ce[(size_t)row*32 + lane] =
                    __float2half_rn(sC[warp][r*32 + lane] + sBias[lane]);
        }
        __syncwarp();
    }
}

// ---- aggregation: warp per node; writes enew back into g_ce (handoff) ------------
// launch_bounds(256, 6): cap regs (~42) -> 6 blocks/SM -> 75% occupancy ceiling.
__global__ void __launch_bounds__(256, 6)
agg2(int curSlot, int n)
{
    int lane = threadIdx.x & 31;

    __shared__ float sE[32], qE[32], sH[32], qH[32];
    if (threadIdx.x < 32) {
        sE[threadIdx.x] = 0.f; qE[threadIdx.x] = 0.f;
        sH[threadIdx.x] = 0.f; qH[threadIdx.x] = 0.f;
    }
    __syncthreads();

    const float2* bv2 = (const float2*)g_BV;
    float ls = 0.f, lq = 0.f, hs = 0.f, hq = 0.f;
    int d = blockIdx.x * (blockDim.x >> 5) + (threadIdx.x >> 5);
    if (d < n) {
        int beg = g_rowptr[d], end = g_rowptr[d+1];
        float ah = g_Ah[d*H + lane];
        float uh = g_Uh[d*H + lane];
        float num = 0.f, den = 0.f;
        int i = beg;
        for (; i + 3 < end; i += 4) {
            int     s[4];
            float   ce[4];
            float2  bv[4];
            __half* cp[4];
            #pragma unroll
            for (int j = 0; j < 4; j++) s[j] = g_ssrc[i+j];
            #pragma unroll
            for (int j = 0; j < 4; j++) {
                cp[j] = &g_ce[(size_t)(i+j)*H + lane];
                ce[j] = __half2float(*cp[j]);
            }
            #pragma unroll
            for (int j = 0; j < 4; j++) bv[j] = bv2[s[j]*H + lane];
            #pragma unroll
            for (int j = 0; j < 4; j++) {
                float en = ah + bv[j].x + ce[j];
                *cp[j] = __float2half_rn(en);          // handoff: enew
                ls += en; lq += en * en;
                float sg = 1.0f / (1.0f + __expf(-en));
                num += sg * bv[j].y;
                den += sg;
            }
        }
        for (; i < end; i++) {
            int s0 = g_ssrc[i];
            __half* cp = &g_ce[(size_t)i*H + lane];
            float2 bv = bv2[s0*H + lane];
            float en = ah + bv.x + __half2float(*cp);
            *cp = __float2half_rn(en);                 // handoff: enew
            ls += en; lq += en * en;
            float sg0 = 1.0f / (1.0f + __expf(-en));
            num += sg0 * bv.y;
            den += sg0;
        }
        float hn = uh + num / (den + 1e-6f);
        g_hnew[d*H + lane] = hn;
        hs += hn; hq += hn * hn;
    }
    atomicAdd(&sH[lane], hs); atomicAdd(&qH[lane], hq);
    atomicAdd(&sE[lane], ls); atomicAdd(&qE[lane], lq);
    __syncthreads();
    if (threadIdx.x < 32) {
        atomicAdd(&g_stats[curSlot*128 + threadIdx.x],      sH[threadIdx.x]);
        atomicAdd(&g_stats[curSlot*128 + 32 + threadIdx.x], qH[threadIdx.x]);
        atomicAdd(&g_stats[curSlot*128 + 64 + threadIdx.x], sE[threadIdx.x]);
        atomicAdd(&g_stats[curSlot*128 + 96 + threadIdx.x], qE[threadIdx.x]);
    }
}

// ---- score pre-pass: final h-update fused; hid_src -> g_Ah, hid_dst -> g_Bh ------
__global__ void __launch_bounds__(128)
score_gemm2(const float* __restrict__ W1, const float* __restrict__ b1,
            const float* __restrict__ bng, const float* __restrict__ bnb,
            int statSlot, int n)
{
    int lane = threadIdx.x & 31;
    float ws[32], wd[32];
    #pragma unroll
    for (int k = 0; k < 32; k++) {
        ws[k] = W1[k*32 + lane];
        wd[k] = W1[(32 + k)*32 + lane];
    }
    float bb = b1[lane];
    float inv = 1.0f / (float)n;
    float s1 = g_stats[statSlot*128 + lane];
    float s2 = g_stats[statSlot*128 + 32 + lane];
    float mn = s1 * inv;
    float var = s2 * inv - mn * mn;
    float sc = rsqrtf(var + 1e-5f) * bng[lane];
    float bt = bnb[lane];

    int warp0  = blockIdx.x * (blockDim.x >> 5) + (threadIdx.x >> 5);
    int stride = gridDim.x * (blockDim.x >> 5);
    for (int row = warp0; row < n; row += stride) {
        float hv = g_h[row*H + lane];
        hv += fmaxf((g_hnew[row*H + lane] - mn) * sc + bt, 0.f);
        float a = bb, c = 0.f;
        #pragma unroll
        for (int k = 0; k < 32; k++) {
            float hk = __shfl_sync(FULL, hv, k);
            a += hk * ws[k];
            c += hk * wd[k];
        }
        g_Ah[row*H + lane] = a;
        g_Bh[row*H + lane] = c;
    }
}

// ---- score: hid = relu(hid_s + hid_d + hid_e); out = hid @ W2 + b2 ---------------
__global__ void score_final(const float* __restrict__ W2, const float* __restrict__ b2,
                            float* __restrict__ out, int ne)
{
    int lane = threadIdx.x & 31;
    float w2 = W2[lane];
    float bb2 = b2[0];

    int i = blockIdx.x * (blockDim.x >> 5) + (threadIdx.x >> 5);
    if (i >= ne) return;
    int s = g_ssrc[i], d = g_sdst[i], o = g_oid[i];
    float hid = g_Ah[s*H + lane] + g_Bh[d*H + lane]
              + __half2float(g_ce[(size_t)i*H + lane]);
    hid = fmaxf(hid, 0.f);
    float p = hid * w2;
    #pragma unroll
    for (int off = 16; off > 0; off >>= 1)
        p += __shfl_xor_sync(FULL, p, off);
    if (lane == 0) out[o] = p + bb2;
}

// ==================================================================================
extern "C" void kernel_launch(void* const* d_in, const int* in_sizes, int n_in,
                              void* d_out, int out_size)
{
    const float* x    = (const float*)d_in[0];
    const float* ein  = (const float*)d_in[1];
    const int*   eidx = (const int*)  d_in[2];
    const float* pe_w = (const float*)d_in[3];
    const float* pe_b = (const float*)d_in[4];
    const float* ed_w = (const float*)d_in[5];
    const float* ed_b = (const float*)d_in[6];
    const float* A_w  = (const float*)d_in[7];
    const float* A_b  = (const float*)d_in[8];
    const float* B_w  = (const float*)d_in[9];
    const float* B_b  = (const float*)d_in[10];
    const float* C_w  = (const float*)d_in[11];
    const float* C_b  = (const float*)d_in[12];
    const float* U_w  = (const float*)d_in[13];
    const float* U_b  = (const float*)d_in[14];
    const float* V_w  = (const float*)d_in[15];
    const float* V_b  = (const float*)d_in[16];
    const float* bnhg = (const float*)d_in[17];
    const float* bnhb = (const float*)d_in[18];
    const float* bneg = (const float*)d_in[19];
    const float* bneb = (const float*)d_in[20];
    const float* W1_w = (const float*)d_in[21];
    const float* W1_b = (const float*)d_in[22];
    const float* W2_w = (const float*)d_in[23];
    const float* W2_b = (const float*)d_in[24];
    float* out = (float*)d_out;

    const int n  = in_sizes[0];
    const int ne = in_sizes[1];
    const int* src = eidx;
    const int* dst = eidx + ne;
    const float inv_ne = 1.0f / (float)ne;

    const int TB = 256;
    const int WPB = TB / 32;
    const int G_NODE_W = (n  + WPB - 1) / WPB;
    const int G_EDGE_W = (ne + WPB - 1) / WPB;
    const int G_MMA = 1480;
    const int G_G4  = 1480;

    // ---- fused CSR build: 1 launch ----
    setup_fused<<<SCAN_NB, 1024>>>(src, dst, ne);

    for (int l = 0; l < NL; l++) {
        // eMode 2 reads enew_{l-1} straight from g_ce (agg2 handoff); no gathers.
        ce_mma<<<G_MMA, 128>>>(C_w + l*H*H, C_b + l*H,
                               bneg + (l-1)*H, bneb + (l-1)*H,
                               ein, ed_w, ed_b,
                               l-1, l == 0 ? 1 : 2, /*writeE=*/1, ne, inv_ne);

        gemm4_fused<<<G_G4, 128>>>(A_w + l*H*H, A_b + l*H,
                                   B_w + l*H*H, B_b + l*H,
                                   U_w + l*H*H, U_b + l*H,
                                   V_w + l*H*H, V_b + l*H,
                                   bnhg + (l-1)*H, bnhb + (l-1)*H,
                                   x, pe_w, pe_b,
                                   l-1, l == 0 ? 0 : 1, n);

        agg2<<<G_NODE_W, TB>>>(l, n);      // launch #4 on l=0 -> profiled
    }

    // final edge term: reads enew_3 from g_ce handoff; GEMM with W1[64:96] -> hid_e
    ce_mma<<<G_MMA, 128>>>(W1_w + 64*32, (const float*)nullptr,
                           bneg + (NL-1)*H, bneb + (NL-1)*H,
                           (const float*)nullptr, (const float*)nullptr,
                           (const float*)nullptr,
                           NL-1, /*eMode=*/2, /*writeE=*/0, ne, inv_ne);
    score_gemm2<<<G_G4, 128>>>(W1_w, W1_b,
                               bnhg + (NL-1)*H, bnhb + (NL-1)*H, NL-1, n);
    score_final<<<G_EDGE_W, TB>>>(W2_w, W2_b, out, ne);
}

// round 17
// speedup vs baseline: 1.4280x; 1.0227x over previous
#include <cuda_runtime.h>
#include <cuda_fp16.h>
#include <mma.h>
#include <math.h>

using namespace nvcuda;

#define NN 100000
#define EE 800000
#define H  32
#define NL 4
#define FULL 0xffffffffu
#define SCAN_N   (NN + 1)
#define SCAN_NB  ((SCAN_N + 1023) / 1024)

// ---------------- scratch ---------------------------------------------------------
__device__ float  g_h[NN*H];
__device__ float  g_hnew[NN*H];
__device__ float  g_Ah[NN*H];      // includes A_b + C_b (fold); feeds agg2 only
__device__ float  g_Bh[NN*H];      // score pre-pass output (hid_dst)
__device__ float  g_Uh[NN*H];
__device__ float  g_BV[NN*H*2];    // interleaved {Bh,Vh} for agg2 gathers
__device__ __half g_e[EE*H];       // e_l (dst-sorted)
__device__ __half g_ce[EE*H];      // ce_mma writes Ce; agg2 overwrites with enew (handoff)
__device__ float  g_esrt[EE];      // ein presorted to dst-order (coalesced eMode1 reads)
// stats slots: per layer l: [l*128 + 0:64) h sum/sq, [l*128+64:128) e sum/sq
__device__ float  g_stats[NL*128];
__device__ int    g_hist[SCAN_NB*1024];   // zero at load; scan re-zeros (leave-clean)
__device__ int    g_rowptr[NN+1];
__device__ int    g_cursor[NN];
__device__ int    g_bsum[SCAN_NB];
__device__ int    g_bar[4];               // spin-barrier counters (self-cleaning)
__device__ int    g_ssrc[EE];
__device__ int    g_sdst[EE];
__device__ int    g_oid[EE];

// ---------------- setup part 1: hist -> scan (spin barriers, co-resident) ---------
__global__ void __launch_bounds__(1024)
setup_hist_scan(const int* __restrict__ dst, int ne)
{
    __shared__ int sm[1024];
    int b = blockIdx.x, t = threadIdx.x;
    int nb = gridDim.x;
    int gid = b*1024 + t;
    int gsz = nb*1024;

    if (gid < NL*128) g_stats[gid] = 0.f;

    for (int i = gid; i < ne; i += gsz)
        atomicAdd(&g_hist[dst[i]], 1);

    __syncthreads();
    if (t == 0) {
        __threadfence();
        atomicAdd(&g_bar[0], 1);
        while (atomicAdd(&g_bar[0], 0) < nb) __nanosleep(64);
    }
    __syncthreads();

    int idx = gid;
    int v = (idx < SCAN_N) ? g_hist[idx] : 0;
    if (idx < SCAN_N) g_hist[idx] = 0;
    sm[t] = v;
    __syncthreads();
    for (int off = 1; off < 1024; off <<= 1) {
        int u = (t >= off) ? sm[t - off] : 0;
        __syncthreads();
        sm[t] += u;
        __syncthreads();
    }
    if (t == 1023) g_bsum[b] = sm[1023];
    __syncthreads();
    if (t == 0) {
        __threadfence();
        atomicAdd(&g_bar[1], 1);
        while (atomicAdd(&g_bar[1], 0) < nb) __nanosleep(64);
    }
    __syncthreads();
    int pre = 0;
    for (int i = 0; i < b; i++) pre += g_bsum[i];
    int excl = pre + sm[t] - v;
    if (idx < SCAN_N) {
        g_rowptr[idx] = excl;
        if (idx < NN) g_cursor[idx] = excl;
    }
    __syncthreads();
    if (t == 0) {
        int done = atomicAdd(&g_bar[2], 1);
        if (done == nb - 1) {
            g_bar[0] = 0; g_bar[1] = 0; g_bar[2] = 0;
            __threadfence();
        }
    }
}

// ---------------- setup part 2: scatter (also presorts ein) ----------------------
__global__ void scatter_kernel(const int* __restrict__ src, const int* __restrict__ dst,
                               const float* __restrict__ ein, int ne)
{
    for (int i = blockIdx.x * blockDim.x + threadIdx.x; i < ne;
         i += gridDim.x * blockDim.x) {
        int d = dst[i];
        int pos = atomicAdd(&g_cursor[d], 1);
        g_ssrc[pos] = src[i];
        g_sdst[pos] = d;
        g_oid[pos]  = i;
        g_esrt[pos] = ein[i];
    }
}

// ------- gemm4: weights in REGISTERS; Ah bias = A_b + C_b (C-bias fold) ----------
__global__ void __launch_bounds__(128)
gemm4_fused(const float* __restrict__ Aw, const float* __restrict__ Ab,
            const float* __restrict__ Cb,
            const float* __restrict__ Bw, const float* __restrict__ Bb,
            const float* __restrict__ Uw, const float* __restrict__ Ub,
            const float* __restrict__ Vw, const float* __restrict__ Vb,
            const float* __restrict__ bng, const float* __restrict__ bnb,
            const float* __restrict__ x,
            const float* __restrict__ pw, const float* __restrict__ pb,
            int statSlot, int mode /*0=proj,1=update*/, int n)
{
    int lane = threadIdx.x & 31;
    float wA[32], wB[32], wU[32], wV[32];
    #pragma unroll
    for (int k = 0; k < 32; k++) {
        wA[k] = Aw[k*H + lane];
        wB[k] = Bw[k*H + lane];
        wU[k] = Uw[k*H + lane];
        wV[k] = Vw[k*H + lane];
    }
    float bA = Ab[lane] + Cb[lane];   // C-bias fold: enew = Ah[d]+Bh[s]+Ce_nobias
    float bB = Bb[lane], bU = Ub[lane], bV = Vb[lane];

    float mn = 0.f, sc = 0.f, bt = 0.f, pwl = 0.f, pbl = 0.f;
    if (mode == 1) {
        float inv = 1.0f / (float)n;
        float s1 = g_stats[statSlot*128 + lane];
        float s2 = g_stats[statSlot*128 + 32 + lane];
        mn = s1 * inv;
        float var = s2 * inv - mn * mn;
        sc = rsqrtf(var + 1e-5f) * bng[lane];
        bt = bnb[lane];
    } else {
        pwl = pw[lane]; pbl = pb[lane];
    }

    float2* bv2 = (float2*)g_BV;
    int warp0  = blockIdx.x * (blockDim.x >> 5) + (threadIdx.x >> 5);
    int stride = gridDim.x * (blockDim.x >> 5);
    for (int row = warp0; row < n; row += stride) {
        float hv;
        if (mode == 0) {
            hv = x[row] * pwl + pbl;
            g_h[row*H + lane] = hv;
        } else {
            hv = g_h[row*H + lane];
            float v = (g_hnew[row*H + lane] - mn) * sc + bt;
            hv += fmaxf(v, 0.f);
            g_h[row*H + lane] = hv;
        }
        float a = bA, b = bB, u = bU, v = bV;
        #pragma unroll
        for (int k = 0; k < 32; k++) {
            float hk = __shfl_sync(FULL, hv, k);
            a += hk * wA[k];
            b += hk * wB[k];
            u += hk * wU[k];
            v += hk * wV[k];
        }
        g_Ah[row*H + lane] = a;
        g_Uh[row*H + lane] = u;
        bv2[row*H + lane] = make_float2(b, v);
    }
}

// ---- tensor-core edge GEMM -> fp16 ce (NO bias; folded into Ah). N-split.
// eMode 1: project e from presorted input (coalesced); store ce.
// eMode 2: g_ce holds enew_{l-1} (agg2 handoff): e += relu(BN(enew)); write e
//          iff writeE; GEMM overwrites g_ce with this layer's Ce.
__global__ void __launch_bounds__(128)
ce_mma(const float* __restrict__ W,
       const float* __restrict__ bng, const float* __restrict__ bnb,
       const float* __restrict__ ew, const float* __restrict__ eb,
       int prevSlot, int eMode, int writeE, int ne, float inv_ne)
{
    __shared__ __half sWhi[32*32], sWlo[32*32];
    __shared__ __half sE[4][16*32];
    __shared__ float  sC[4][16*32];
    __shared__ float  sMn[32], sSc[32], sBt[32], sEw[32], sEb[32];

    int tid = threadIdx.x;
    for (int i = tid; i < 1024; i += 128) {
        float w = W[i];
        __half hi = __float2half_rn(w);
        sWhi[i] = hi;
        sWlo[i] = __float2half_rn(w - __half2float(hi));
    }
    if (tid < 32) {
        sMn[tid] = 0.f; sSc[tid] = 0.f; sBt[tid] = 0.f;
        sEw[tid] = 0.f; sEb[tid] = 0.f;
        if (eMode == 2) {
            float s1 = g_stats[prevSlot*128 + 64 + tid];
            float s2 = g_stats[prevSlot*128 + 96 + tid];
            float mean = s1 * inv_ne;
            float var  = s2 * inv_ne - mean * mean;
            sMn[tid] = mean;
            sSc[tid] = rsqrtf(var + 1e-5f) * bng[tid];
            sBt[tid] = bnb[tid];
        } else {
            sEw[tid] = ew[tid]; sEb[tid] = eb[tid];
        }
    }
    __syncthreads();

    int warp = tid >> 5, lane = tid & 31;

    __half2* e2  = (__half2*)g_e;
    __half2* ce2 = (__half2*)g_ce;
    int ntiles = (ne + 63) >> 6;

    for (int t = blockIdx.x; t < ntiles; t += gridDim.x) {
        int rbase = t*64 + warp*16;
        __half2* stage = (__half2*)sE[warp];
        #pragma unroll
        for (int i = 0; i < 8; i++) {
            int idx = i*32 + lane;
            int row = rbase + (idx >> 4);
            int ch  = idx & 15;
            if (row < ne) {
                size_t g = (size_t)row*16 + ch;
                if (eMode == 1) {
                    float xin = g_esrt[row];       // presorted: coalesced
                    int c = ch*2;
                    __half2 nv = __floats2half2_rn(xin*sEw[c] + sEb[c],
                                                   xin*sEw[c+1] + sEb[c+1]);
                    e2[g] = nv;
                    stage[idx] = nv;
                } else {
                    int c = ch*2;
                    float2 en = __half22float2(ce2[g]);   // enew_{l-1} via handoff
                    float2 f  = __half22float2(e2[g]);
                    f.x += fmaxf((en.x - sMn[c])   * sSc[c]   + sBt[c],   0.f);
                    f.y += fmaxf((en.y - sMn[c+1]) * sSc[c+1] + sBt[c+1], 0.f);
                    __half2 nv = __floats2half2_rn(f.x, f.y);
                    if (writeE) e2[g] = nv;
                    stage[idx] = nv;
                }
            } else {
                stage[idx] = __floats2half2_rn(0.f, 0.f);
            }
        }
        __syncwarp();

        wmma::fragment<wmma::matrix_a, 16,16,16, __half, wmma::row_major> a0, a1;
        wmma::load_matrix_sync(a0, sE[warp],      32);
        wmma::load_matrix_sync(a1, sE[warp] + 16, 32);

        #pragma unroll 1
        for (int nh = 0; nh < 2; nh++) {
            wmma::fragment<wmma::matrix_b, 16,16,16, __half, wmma::row_major> fbh0, fbh1, fbl0, fbl1;
            wmma::load_matrix_sync(fbh0, sWhi + nh*16,           32);
            wmma::load_matrix_sync(fbh1, sWhi + 16*32 + nh*16,   32);
            wmma::load_matrix_sync(fbl0, sWlo + nh*16,           32);
            wmma::load_matrix_sync(fbl1, sWlo + 16*32 + nh*16,   32);

            wmma::fragment<wmma::accumulator, 16,16,16, float> acc;
            wmma::fill_fragment(acc, 0.f);
            wmma::mma_sync(acc, a0, fbh0, acc);
            wmma::mma_sync(acc, a1, fbh1, acc);
            wmma::mma_sync(acc, a0, fbl0, acc);
            wmma::mma_sync(acc, a1, fbl1, acc);

            wmma::store_matrix_sync(sC[warp] + nh*16, acc, 32, wmma::mem_row_major);
        }
        __syncwarp();

        // epilogue: half2 conversion, 8 iterations (256 half2 slots per 16 rows)
        const float2* sc2 = (const float2*)sC[warp];
        #pragma unroll
        for (int i = 0; i < 8; i++) {
            int idx = i*32 + lane;
            int row = rbase + (idx >> 4);
            if (row < ne) {
                float2 v = sc2[idx];
                ce2[(size_t)row*16 + (idx & 15)] = __floats2half2_rn(v.x, v.y);
            }
        }
        __syncwarp();
    }
}

// ---- aggregation: warp per node; writes enew back into g_ce (handoff) ------------
__global__ void __launch_bounds__(256, 6)
agg2(int curSlot, int n)
{
    int lane = threadIdx.x & 31;

    __shared__ float sE[32], qE[32], sH[32], qH[32];
    if (threadIdx.x < 32) {
        sE[threadIdx.x] = 0.f; qE[threadIdx.x] = 0.f;
        sH[threadIdx.x] = 0.f; qH[threadIdx.x] = 0.f;
    }
    __syncthreads();

    const float2* bv2 = (const float2*)g_BV;
    float ls = 0.f, lq = 0.f, hs = 0.f, hq = 0.f;
    int d = blockIdx.x * (blockDim.x >> 5) + (threadIdx.x >> 5);
    if (d < n) {
        int beg = g_rowptr[d], end = g_rowptr[d+1];
        float ah = g_Ah[d*H + lane];
        float uh = g_Uh[d*H + lane];
        float num = 0.f, den = 0.f;
        int i = beg;
        for (; i + 3 < end; i += 4) {
            int     s[4];
            float   ce[4];
            float2  bv[4];
            __half* cp[4];
            #pragma unroll
            for (int j = 0; j < 4; j++) s[j] = g_ssrc[i+j];
            #pragma unroll
            for (int j = 0; j < 4; j++) {
                cp[j] = &g_ce[(size_t)(i+j)*H + lane];
                ce[j] = __half2float(*cp[j]);
            }
            #pragma unroll
            for (int j = 0; j < 4; j++) bv[j] = bv2[s[j]*H + lane];
            #pragma unroll
            for (int j = 0; j < 4; j++) {
                float en = ah + bv[j].x + ce[j];
                *cp[j] = __float2half_rn(en);          // handoff: enew
                ls += en; lq += en * en;
                float sg = 1.0f / (1.0f + __expf(-en));
                num += sg * bv[j].y;
                den += sg;
            }
        }
        for (; i < end; i++) {
            int s0 = g_ssrc[i];
            __half* cp = &g_ce[(size_t)i*H + lane];
            float2 bv = bv2[s0*H + lane];
            float en = ah + bv.x + __half2float(*cp);
            *cp = __float2half_rn(en);                 // handoff: enew
            ls += en; lq += en * en;
            float sg0 = 1.0f / (1.0f + __expf(-en));
            num += sg0 * bv.y;
            den += sg0;
        }
        float hn = uh + num / (den + 1e-6f);
        g_hnew[d*H + lane] = hn;
        hs += hn; hq += hn * hn;
    }
    atomicAdd(&sH[lane], hs); atomicAdd(&qH[lane], hq);
    atomicAdd(&sE[lane], ls); atomicAdd(&qE[lane], lq);
    __syncthreads();
    if (threadIdx.x < 32) {
        atomicAdd(&g_stats[curSlot*128 + threadIdx.x],      sH[threadIdx.x]);
        atomicAdd(&g_stats[curSlot*128 + 32 + threadIdx.x], qH[threadIdx.x]);
        atomicAdd(&g_stats[curSlot*128 + 64 + threadIdx.x], sE[threadIdx.x]);
        atomicAdd(&g_stats[curSlot*128 + 96 + threadIdx.x], qE[threadIdx.x]);
    }
}

// ---- score pre-pass: final h-update fused; hid_src -> g_Ah, hid_dst -> g_Bh ------
__global__ void __launch_bounds__(128)
score_gemm2(const float* __restrict__ W1, const float* __restrict__ b1,
            const float* __restrict__ bng, const float* __restrict__ bnb,
            int statSlot, int n)
{
    int lane = threadIdx.x & 31;
    float ws[32], wd[32];
    #pragma unroll
    for (int k = 0; k < 32; k++) {
        ws[k] = W1[k*32 + lane];
        wd[k] = W1[(32 + k)*32 + lane];
    }
    float bb = b1[lane];
    float inv = 1.0f / (float)n;
    float s1 = g_stats[statSlot*128 + lane];
    float s2 = g_stats[statSlot*128 + 32 + lane];
    float mn = s1 * inv;
    float var = s2 * inv - mn * mn;
    float sc = rsqrtf(var + 1e-5f) * bng[lane];
    float bt = bnb[lane];

    int warp0  = blockIdx.x * (blockDim.x >> 5) + (threadIdx.x >> 5);
    int stride = gridDim.x * (blockDim.x >> 5);
    for (int row = warp0; row < n; row += stride) {
        float hv = g_h[row*H + lane];
        hv += fmaxf((g_hnew[row*H + lane] - mn) * sc + bt, 0.f);
        float a = bb, c = 0.f;
        #pragma unroll
        for (int k = 0; k < 32; k++) {
            float hk = __shfl_sync(FULL, hv, k);
            a += hk * ws[k];
            c += hk * wd[k];
        }
        g_Ah[row*H + lane] = a;
        g_Bh[row*H + lane] = c;
    }
}

// ---- score: hid = relu(hid_s + hid_d + hid_e); out = hid @ W2 + b2 ---------------
__global__ void score_final(const float* __restrict__ W2, const float* __restrict__ b2,
                            float* __restrict__ out, int ne)
{
    int lane = threadIdx.x & 31;
    float w2 = W2[lane];
    float bb2 = b2[0];

    int i = blockIdx.x * (blockDim.x >> 5) + (threadIdx.x >> 5);
    if (i >= ne) return;
    int s = g_ssrc[i], d = g_sdst[i], o = g_oid[i];
    float hid = g_Ah[s*H + lane] + g_Bh[d*H + lane]
              + __half2float(g_ce[(size_t)i*H + lane]);
    hid = fmaxf(hid, 0.f);
    float p = hid * w2;
    #pragma unroll
    for (int off = 16; off > 0; off >>= 1)
        p += __shfl_xor_sync(FULL, p, off);
    if (lane == 0) out[o] = p + bb2;
}

// ==================================================================================
extern "C" void kernel_launch(void* const* d_in, const int* in_sizes, int n_in,
                              void* d_out, int out_size)
{
    const float* x    = (const float*)d_in[0];
    const float* ein  = (const float*)d_in[1];
    const int*   eidx = (const int*)  d_in[2];
    const float* pe_w = (const float*)d_in[3];
    const float* pe_b = (const float*)d_in[4];
    const float* ed_w = (const float*)d_in[5];
    const float* ed_b = (const float*)d_in[6];
    const float* A_w  = (const float*)d_in[7];
    const float* A_b  = (const float*)d_in[8];
    const float* B_w  = (const float*)d_in[9];
    const float* B_b  = (const float*)d_in[10];
    const float* C_w  = (const float*)d_in[11];
    const float* C_b  = (const float*)d_in[12];
    const float* U_w  = (const float*)d_in[13];
    const float* U_b  = (const float*)d_in[14];
    const float* V_w  = (const float*)d_in[15];
    const float* V_b  = (const float*)d_in[16];
    const float* bnhg = (const float*)d_in[17];
    const float* bnhb = (const float*)d_in[18];
    const float* bneg = (const float*)d_in[19];
    const float* bneb = (const float*)d_in[20];
    const float* W1_w = (const float*)d_in[21];
    const float* W1_b = (const float*)d_in[22];
    const float* W2_w = (const float*)d_in[23];
    const float* W2_b = (const float*)d_in[24];
    float* out = (float*)d_out;

    const int n  = in_sizes[0];
    const int ne = in_sizes[1];
    const int* src = eidx;
    const int* dst = eidx + ne;
    const float inv_ne = 1.0f / (float)ne;

    const int TB = 256;
    const int WPB = TB / 32;
    const int G_NODE_W = (n  + WPB - 1) / WPB;
    const int G_EDGE_W = (ne + WPB - 1) / WPB;
    const int G_MMA = 1480;
    const int G_G4  = 1480;

    // ---- CSR build: 2 launches (split so gemm4 lands in profile slot #4) ----
    setup_hist_scan<<<SCAN_NB, 1024>>>(dst, ne);                 // #1
    scatter_kernel<<<800, TB>>>(src, dst, ein, ne);              // #2

    for (int l = 0; l < NL; l++) {
        // ce_mma(l) and gemm4(l) are independent (handoff removed Ah/Bh reads).
        ce_mma<<<G_MMA, 128>>>(C_w + l*H*H,                      // #3 = ce_mma(l0)
                               bneg + (l-1)*H, bneb + (l-1)*H,
                               ed_w, ed_b,
                               l-1, l == 0 ? 1 : 2, /*writeE=*/1, ne, inv_ne);

        gemm4_fused<<<G_G4, 128>>>(A_w + l*H*H, A_b + l*H, C_b + l*H,  // #4 <- ncu
                                   B_w + l*H*H, B_b + l*H,
                                   U_w + l*H*H, U_b + l*H,
                                   V_w + l*H*H, V_b + l*H,
                                   bnhg + (l-1)*H, bnhb + (l-1)*H,
                                   x, pe_w, pe_b,
                                   l-1, l == 0 ? 0 : 1, n);

        agg2<<<G_NODE_W, TB>>>(l, n);
    }

    // final edge term: reads enew_3 from g_ce handoff; GEMM with W1[64:96] -> hid_e
    ce_mma<<<G_MMA, 128>>>(W1_w + 64*32,
                           bneg + (NL-1)*H, bneb + (NL-1)*H,
                           (const float*)nullptr, (const float*)nullptr,
                           NL-1, /*eMode=*/2, /*writeE=*/0, ne, inv_ne);
    score_gemm2<<<G_G4, 128>>>(W1_w, W1_b,
                               bnhg + (NL-1)*H, bnhb + (NL-1)*H, NL-1, n);
    score_final<<<G_EDGE_W, TB>>>(W2_w, W2_b, out, ne);
}